// round 2
// baseline (speedup 1.0000x reference)
#include <cuda_runtime.h>
#include <cuda_bf16.h>
#include <math_constants.h>

// Problem constants
#define IN_F   1024
#define OUT_F  2048
#define BATCH  8192
#define LR     0.02f
#define ANTI   0.4f
#define PREC   1e-30f

// ---------------- scratch (no allocations allowed) ----------------
__device__ float        g_ds[(size_t)OUT_F * IN_F];
__device__ int          g_idx0[BATCH];
__device__ int          g_idx1[BATCH];
__device__ unsigned int g_nc;

// ---------------- SGEMM: C[M,N] = A[M,K] * B[N,K]^T  (NT, fp32) ----------------
#define BM 128
#define BN 128
#define BK 16
#define TM 8
#define TN 8

__global__ __launch_bounds__(256, 2)
void gemm_nt_kernel(const float* __restrict__ A, const float* __restrict__ B,
                    float* __restrict__ C, int M, int N, int K) {
    __shared__ float As[BK][BM];
    __shared__ float Bs[BK][BN];

    const int tid = threadIdx.x;
    const int m0 = blockIdx.y * BM;
    const int n0 = blockIdx.x * BN;
    const int threadRow = tid / 16;   // 0..15
    const int threadCol = tid % 16;   // 0..15

    float acc[TM][TN];
    #pragma unroll
    for (int i = 0; i < TM; i++)
        #pragma unroll
        for (int j = 0; j < TN; j++) acc[i][j] = 0.f;

    float regM[TM], regN[TN];

    for (int k0 = 0; k0 < K; k0 += BK) {
        // Load A tile (BM x BK) and B tile (BN x BK), both K-major, as float4s.
        // 128 rows * 4 float4s/row = 512 float4s; 256 threads -> 2 each.
        #pragma unroll
        for (int r = 0; r < 2; r++) {
            int f   = tid + r * 256;     // 0..511
            int row = f >> 2;            // 0..127
            int kq  = f & 3;             // which float4 in the 16-wide K slab
            float4 va = *reinterpret_cast<const float4*>(
                &A[(size_t)(m0 + row) * K + k0 + kq * 4]);
            As[kq * 4 + 0][row] = va.x;
            As[kq * 4 + 1][row] = va.y;
            As[kq * 4 + 2][row] = va.z;
            As[kq * 4 + 3][row] = va.w;
            float4 vb = *reinterpret_cast<const float4*>(
                &B[(size_t)(n0 + row) * K + k0 + kq * 4]);
            Bs[kq * 4 + 0][row] = vb.x;
            Bs[kq * 4 + 1][row] = vb.y;
            Bs[kq * 4 + 2][row] = vb.z;
            Bs[kq * 4 + 3][row] = vb.w;
        }
        __syncthreads();

        #pragma unroll
        for (int kk = 0; kk < BK; kk++) {
            #pragma unroll
            for (int i = 0; i < TM; i++) regM[i] = As[kk][threadRow * TM + i];
            #pragma unroll
            for (int j = 0; j < TN; j++) regN[j] = Bs[kk][threadCol * TN + j];
            #pragma unroll
            for (int i = 0; i < TM; i++)
                #pragma unroll
                for (int j = 0; j < TN; j++)
                    acc[i][j] = fmaf(regM[i], regN[j], acc[i][j]);
        }
        __syncthreads();
    }

    // Write back (float4)
    #pragma unroll
    for (int i = 0; i < TM; i++) {
        int m = m0 + threadRow * TM + i;
        #pragma unroll
        for (int j = 0; j < TN; j += 4) {
            float4 v = make_float4(acc[i][j], acc[i][j + 1], acc[i][j + 2], acc[i][j + 3]);
            *reinterpret_cast<float4*>(&C[(size_t)m * N + n0 + threadCol * TN + j]) = v;
        }
    }
}

// ---------------- Top-2 per batch row of y [BATCH, OUT_F] ----------------
__device__ __forceinline__ void merge_top2(float& av1, int& ai1, float& av2, int& ai2,
                                           float bv1, int bi1, float bv2, int bi2) {
    if (bv1 > av1 || (bv1 == av1 && bi1 < ai1)) {
        float nv2; int ni2;
        if (av1 > bv2 || (av1 == bv2 && ai1 < bi2)) { nv2 = av1; ni2 = ai1; }
        else                                         { nv2 = bv2; ni2 = bi2; }
        av1 = bv1; ai1 = bi1; av2 = nv2; ai2 = ni2;
    } else {
        if (bv1 > av2 || (bv1 == av2 && bi1 < ai2)) { av2 = bv1; ai2 = bi1; }
    }
}

__global__ __launch_bounds__(256)
void top2_kernel(const float* __restrict__ y, int N) {
    const int b   = blockIdx.x;
    const int tid = threadIdx.x;
    // reset nc seed for this launch (stream-ordered before update_kernel)
    if (b == 0 && tid == 0) g_nc = __float_as_uint(PREC);

    const float* row = y + (size_t)b * N;
    float v1 = -CUDART_INF_F, v2 = -CUDART_INF_F;
    int   i1 = 0x7fffffff,    i2 = 0x7fffffff;
    for (int j = tid; j < N; j += 256) {
        float v = row[j];
        if (v > v1) { v2 = v1; i2 = i1; v1 = v; i1 = j; }
        else if (v > v2) { v2 = v; i2 = j; }
    }

    __shared__ float sv1[256], sv2[256];
    __shared__ int   si1[256], si2[256];
    sv1[tid] = v1; si1[tid] = i1; sv2[tid] = v2; si2[tid] = i2;
    __syncthreads();
    for (int s = 128; s > 0; s >>= 1) {
        if (tid < s) {
            float av1 = sv1[tid], av2 = sv2[tid];
            int   ai1 = si1[tid], ai2 = si2[tid];
            merge_top2(av1, ai1, av2, ai2, sv1[tid + s], si1[tid + s], sv2[tid + s], si2[tid + s]);
            sv1[tid] = av1; si1[tid] = ai1; sv2[tid] = av2; si2[tid] = ai2;
        }
        __syncthreads();
    }
    if (tid == 0) { g_idx0[b] = si1[0]; g_idx1[b] = si2[0]; }
}

// ---------------- ds = yl@x - xx*W, and nc = max|ds| ----------------
// One block per output unit o. Chunked compaction: scan batches in chunks of
// 256, compact matched (b, coeff) pairs into shared memory, then accumulate
// each matched x-row cooperatively (no per-element atomics).
#define CHUNK 256

__global__ __launch_bounds__(256)
void update_kernel(const float* __restrict__ x, const float* __restrict__ w,
                   const float* __restrict__ y, int B, int OUT) {
    const int o   = blockIdx.x;
    const int tid = threadIdx.x;

    __shared__ float accum[IN_F];
    __shared__ int   mb[CHUNK];     // matched batch indices
    __shared__ float mc[CHUNK];     // matched coefficients
    __shared__ int   mcount;
    __shared__ float sxx;

    for (int i = tid; i < IN_F; i += 256) accum[i] = 0.f;
    if (tid == 0) { sxx = 0.f; }
    __syncthreads();

    float xxloc = 0.f;
    for (int b0 = 0; b0 < B; b0 += CHUNK) {
        if (tid == 0) mcount = 0;
        __syncthreads();
        int b = b0 + tid;
        float c = 0.f;
        if (g_idx0[b] == o)      c = 1.0f;
        else if (g_idx1[b] == o) c = -ANTI;
        if (c != 0.f) {
            int slot = atomicAdd(&mcount, 1);
            mb[slot] = b;
            mc[slot] = c;
            xxloc += c * y[(size_t)b * OUT + o];
        }
        __syncthreads();
        const int n = mcount;
        for (int m = 0; m < n; m++) {
            const float* xr = x + (size_t)mb[m] * IN_F;
            const float cm = mc[m];
            #pragma unroll 4
            for (int i = tid; i < IN_F; i += 256)
                accum[i] = fmaf(cm, xr[i], accum[i]);
        }
        __syncthreads();
    }
    if (xxloc != 0.f) atomicAdd(&sxx, xxloc);
    __syncthreads();

    const float xx = sxx;
    float lmax = 0.f;
    #pragma unroll 4
    for (int i = tid; i < IN_F; i += 256) {
        float d = accum[i] - xx * w[(size_t)o * IN_F + i];
        g_ds[(size_t)o * IN_F + i] = d;
        lmax = fmaxf(lmax, fabsf(d));
    }
    // block-reduce lmax
    #pragma unroll
    for (int off = 16; off > 0; off >>= 1)
        lmax = fmaxf(lmax, __shfl_xor_sync(0xffffffffu, lmax, off));
    __shared__ float smax[8];
    if ((tid & 31) == 0) smax[tid >> 5] = lmax;
    __syncthreads();
    if (tid == 0) {
        float m = smax[0];
        #pragma unroll
        for (int k = 1; k < 8; k++) m = fmaxf(m, smax[k]);
        atomicMax(&g_nc, __float_as_uint(m));   // values >= 0: bit order == float order
    }
}

// ---------------- new_w = w + LR * ds / nc ----------------
__global__ __launch_bounds__(256)
void finalize_kernel(const float* __restrict__ w, float* __restrict__ neww, int n) {
    const float inv = LR / __uint_as_float(g_nc);
    int i = blockIdx.x * blockDim.x + threadIdx.x;
    if (i < n) neww[i] = fmaf(g_ds[i], inv, w[i]);
}

// ---------------- launch ----------------
extern "C" void kernel_launch(void* const* d_in, const int* in_sizes, int n_in,
                              void* d_out, int out_size) {
    const float* x = (const float*)d_in[0];
    const float* w = (const float*)d_in[1];
    // robustness: detect order by size (x = 8192*1024, w = 2048*1024)
    if (n_in >= 2 && in_sizes[0] == OUT_F * IN_F && in_sizes[1] == BATCH * IN_F) {
        w = (const float*)d_in[0];
        x = (const float*)d_in[1];
    }

    float* y_out = (float*)d_out;                       // [BATCH, OUT_F]
    float* w_out = y_out + (size_t)BATCH * OUT_F;       // [OUT_F, IN_F]

    // 1) y = x @ W^T
    {
        dim3 grid(OUT_F / BN, BATCH / BM);
        gemm_nt_kernel<<<grid, 256>>>(x, w, y_out, BATCH, OUT_F, IN_F);
    }
    // 2) top-2 per batch row (+ nc reset)
    top2_kernel<<<BATCH, 256>>>(y_out, OUT_F);
    // 3) ds + global max
    update_kernel<<<OUT_F, 256>>>(x, w, y_out, BATCH, OUT_F);
    // 4) finalize
    {
        int n = OUT_F * IN_F;
        finalize_kernel<<<(n + 255) / 256, 256>>>(w, w_out, n);
    }
}

// round 4
// speedup vs baseline: 1.2141x; 1.2141x over previous
#include <cuda_runtime.h>
#include <cuda_bf16.h>
#include <math_constants.h>
#include <cstdint>

// Problem constants
#define IN_F   1024
#define OUT_F  2048
#define BATCH  8192
#define LR     0.02f
#define ANTI   0.4f
#define PREC   1e-30f

// ---------------- scratch (no allocations allowed) ----------------
__device__ float        g_ds[(size_t)OUT_F * IN_F];
__device__ int          g_idx0[BATCH];
__device__ int          g_idx1[BATCH];
__device__ unsigned int g_nc;
// tf32 split matrices
__device__ float        g_xhi[(size_t)BATCH * IN_F];
__device__ float        g_xlo[(size_t)BATCH * IN_F];
__device__ float        g_whi[(size_t)OUT_F * IN_F];
__device__ float        g_wlo[(size_t)OUT_F * IN_F];

// ================= helpers =================
__device__ __forceinline__ uint32_t smem_u32(const void* p) {
    uint32_t a;
    asm("{ .reg .u64 t; cvta.to.shared.u64 t, %1; cvt.u32.u64 %0, t; }" : "=r"(a) : "l"(p));
    return a;
}
__device__ __forceinline__ void cp16(uint32_t sm, const void* g) {
    asm volatile("cp.async.cg.shared.global [%0], [%1], 16;" :: "r"(sm), "l"(g) : "memory");
}
__device__ __forceinline__ void cp_commit() {
    asm volatile("cp.async.commit_group;" ::: "memory");
}
template <int N>
__device__ __forceinline__ void cp_wait() {
    asm volatile("cp.async.wait_group %0;" :: "n"(N) : "memory");
}
__device__ __forceinline__ float tf32_rn(float v) {
    uint32_t t; asm("cvt.rna.tf32.f32 %0, %1;" : "=r"(t) : "f"(v)); return __uint_as_float(t);
}
__device__ __forceinline__ void mma_tf32(float* d, const uint32_t* a, const uint32_t* b) {
    asm volatile(
        "mma.sync.aligned.m16n8k8.row.col.f32.tf32.tf32.f32 "
        "{%0,%1,%2,%3}, {%4,%5,%6,%7}, {%8,%9}, {%0,%1,%2,%3};"
        : "+f"(d[0]), "+f"(d[1]), "+f"(d[2]), "+f"(d[3])
        : "r"(a[0]), "r"(a[1]), "r"(a[2]), "r"(a[3]), "r"(b[0]), "r"(b[1]));
}

// ================= split kernel: v -> (tf32 hi, tf32 lo) =================
__global__ __launch_bounds__(256)
void split_kernel(const float4* __restrict__ src, float4* __restrict__ hi,
                  float4* __restrict__ lo, int n4) {
    int i = blockIdx.x * blockDim.x + threadIdx.x;
    if (i >= n4) return;
    float4 v = src[i];
    float4 h, l;
    h.x = tf32_rn(v.x); l.x = tf32_rn(v.x - h.x);
    h.y = tf32_rn(v.y); l.y = tf32_rn(v.y - h.y);
    h.z = tf32_rn(v.z); l.z = tf32_rn(v.z - h.z);
    h.w = tf32_rn(v.w); l.w = tf32_rn(v.w - h.w);
    hi[i] = h; lo[i] = l;
}

// ================= tf32 mma.sync GEMM (3-product split folded into K) =====
// C[8192,2048] = X[8192,1024] @ W[2048,1024]^T
// Virtual K = 3*1024: region 0: xhi*whi, region 1: xlo*whi, region 2: xhi*wlo.
#define BM_T 128
#define BN_T 128
#define BK_T 32
#define KSTRIDE 36            // padded row stride in floats (16B-aligned, bank-spread)
#define NCHUNK 96             // 3 * (1024/32)
// smem: A [128][36] f32 = 18432 B, B same; two stages
#define SM_A(s) ((s) * 36864u)
#define SM_B(s) ((s) * 36864u + 18432u)
#define SMEM_GEMM (2u * 36864u)

__global__ __launch_bounds__(256, 2)
void gemm_tf32_kernel(const float* __restrict__ Xhi, const float* __restrict__ Xlo,
                      const float* __restrict__ Whi, const float* __restrict__ Wlo,
                      float* __restrict__ C) {
    extern __shared__ char smem[];
    const uint32_t sb = smem_u32(smem);
    const int tid = threadIdx.x;
    const int wid = tid >> 5;
    const int lane = tid & 31;
    const int gr  = lane >> 2;   // group id 0..7
    const int tig = lane & 3;    // thread-in-group 0..3
    const int warp_m = wid & 1;  // 0..1  (64 rows each)
    const int warp_n = wid >> 1; // 0..3  (32 cols each)
    const int m0 = blockIdx.y * BM_T;
    const int n0 = blockIdx.x * BN_T;

    // loader assignments: 4 iterations each for A and B; idx = tid + c*256
    // row = idx>>3 (0..127), q = idx&7 (16B chunk within 128B row)
    auto issue_chunk = [&](int s, int buf) {
        const int region = s >> 5;
        const int kbase = (s & 31) * BK_T;
        const float* Asrc = (region == 1) ? Xlo : Xhi;
        const float* Bsrc = (region == 2) ? Wlo : Whi;
        #pragma unroll
        for (int c = 0; c < 4; c++) {
            int idx = tid + c * 256;
            int row = idx >> 3, q = idx & 7;
            cp16(sb + SM_A(buf) + (row * KSTRIDE + q * 4) * 4,
                 Asrc + (size_t)(m0 + row) * IN_F + kbase + q * 4);
            cp16(sb + SM_B(buf) + (row * KSTRIDE + q * 4) * 4,
                 Bsrc + (size_t)(n0 + row) * IN_F + kbase + q * 4);
        }
        cp_commit();
    };

    float acc[4][4][4];
    #pragma unroll
    for (int i = 0; i < 4; i++)
        #pragma unroll
        for (int j = 0; j < 4; j++)
            #pragma unroll
            for (int r = 0; r < 4; r++) acc[i][j][r] = 0.f;

    issue_chunk(0, 0);

    for (int s = 0; s < NCHUNK; s++) {
        const int buf = s & 1;
        if (s + 1 < NCHUNK) {
            issue_chunk(s + 1, buf ^ 1);
            cp_wait<1>();
        } else {
            cp_wait<0>();
        }
        __syncthreads();

        const uint32_t abase = sb + SM_A(buf);
        const uint32_t bbase = sb + SM_B(buf);
        #pragma unroll
        for (int ks = 0; ks < 4; ks++) {
            const int k0 = ks * 8;
            uint32_t a[4][4], b[4][2];
            #pragma unroll
            for (int i = 0; i < 4; i++) {
                int mrow = warp_m * 64 + i * 16 + gr;
                uint32_t p0 = abase + (mrow * KSTRIDE + k0 + tig) * 4;
                uint32_t p1 = abase + ((mrow + 8) * KSTRIDE + k0 + tig) * 4;
                asm volatile("ld.shared.b32 %0, [%1];" : "=r"(a[i][0]) : "r"(p0));
                asm volatile("ld.shared.b32 %0, [%1];" : "=r"(a[i][1]) : "r"(p1));
                asm volatile("ld.shared.b32 %0, [%1];" : "=r"(a[i][2]) : "r"(p0 + 16));
                asm volatile("ld.shared.b32 %0, [%1];" : "=r"(a[i][3]) : "r"(p1 + 16));
            }
            #pragma unroll
            for (int j = 0; j < 4; j++) {
                int nrow = warp_n * 32 + j * 8 + gr;
                uint32_t p = bbase + (nrow * KSTRIDE + k0 + tig) * 4;
                asm volatile("ld.shared.b32 %0, [%1];" : "=r"(b[j][0]) : "r"(p));
                asm volatile("ld.shared.b32 %0, [%1];" : "=r"(b[j][1]) : "r"(p + 16));
            }
            #pragma unroll
            for (int i = 0; i < 4; i++)
                #pragma unroll
                for (int j = 0; j < 4; j++)
                    mma_tf32(acc[i][j], a[i], b[j]);
        }
        __syncthreads();
    }

    // writeback: warp tile rows m0+warp_m*64+i*16+{gr,gr+8}, cols n0+warp_n*32+j*8+2*tig
    #pragma unroll
    for (int i = 0; i < 4; i++) {
        int r0 = m0 + warp_m * 64 + i * 16 + gr;
        #pragma unroll
        for (int j = 0; j < 4; j++) {
            int cc = n0 + warp_n * 32 + j * 8 + 2 * tig;
            *reinterpret_cast<float2*>(C + (size_t)r0 * OUT_F + cc) =
                make_float2(acc[i][j][0], acc[i][j][1]);
            *reinterpret_cast<float2*>(C + (size_t)(r0 + 8) * OUT_F + cc) =
                make_float2(acc[i][j][2], acc[i][j][3]);
        }
    }
}

// ---------------- Top-2 per batch row of y [BATCH, OUT_F] ----------------
__device__ __forceinline__ void merge_top2(float& av1, int& ai1, float& av2, int& ai2,
                                           float bv1, int bi1, float bv2, int bi2) {
    if (bv1 > av1 || (bv1 == av1 && bi1 < ai1)) {
        float nv2; int ni2;
        if (av1 > bv2 || (av1 == bv2 && ai1 < bi2)) { nv2 = av1; ni2 = ai1; }
        else                                         { nv2 = bv2; ni2 = bi2; }
        av1 = bv1; ai1 = bi1; av2 = nv2; ai2 = ni2;
    } else {
        if (bv1 > av2 || (bv1 == av2 && bi1 < ai2)) { av2 = bv1; ai2 = bi1; }
    }
}

__global__ __launch_bounds__(256)
void top2_kernel(const float* __restrict__ y, int N) {
    const int b   = blockIdx.x;
    const int tid = threadIdx.x;
    if (b == 0 && tid == 0) g_nc = __float_as_uint(PREC);

    const float* row = y + (size_t)b * N;
    float v1 = -CUDART_INF_F, v2 = -CUDART_INF_F;
    int   i1 = 0x7fffffff,    i2 = 0x7fffffff;
    for (int j = tid; j < N; j += 256) {
        float v = row[j];
        if (v > v1) { v2 = v1; i2 = i1; v1 = v; i1 = j; }
        else if (v > v2) { v2 = v; i2 = j; }
    }

    __shared__ float sv1[256], sv2[256];
    __shared__ int   si1[256], si2[256];
    sv1[tid] = v1; si1[tid] = i1; sv2[tid] = v2; si2[tid] = i2;
    __syncthreads();
    for (int s = 128; s > 0; s >>= 1) {
        if (tid < s) {
            float av1 = sv1[tid], av2 = sv2[tid];
            int   ai1 = si1[tid], ai2 = si2[tid];
            merge_top2(av1, ai1, av2, ai2, sv1[tid + s], si1[tid + s], sv2[tid + s], si2[tid + s]);
            sv1[tid] = av1; si1[tid] = ai1; sv2[tid] = av2; si2[tid] = ai2;
        }
        __syncthreads();
    }
    if (tid == 0) { g_idx0[b] = si1[0]; g_idx1[b] = si2[0]; }
}

// ---------------- ds = yl@x - xx*W, and nc = max|ds| ----------------
#define CHUNK 256
__global__ __launch_bounds__(256)
void update_kernel(const float* __restrict__ x, const float* __restrict__ w,
                   const float* __restrict__ y, int B, int OUT) {
    const int o   = blockIdx.x;
    const int tid = threadIdx.x;

    __shared__ float accum[IN_F];
    __shared__ int   mb[CHUNK];
    __shared__ float mc[CHUNK];
    __shared__ int   mcount;
    __shared__ float sxx;

    for (int i = tid; i < IN_F; i += 256) accum[i] = 0.f;
    if (tid == 0) sxx = 0.f;
    __syncthreads();

    float xxloc = 0.f;
    for (int b0 = 0; b0 < B; b0 += CHUNK) {
        if (tid == 0) mcount = 0;
        __syncthreads();
        int b = b0 + tid;
        float c = 0.f;
        if (g_idx0[b] == o)      c = 1.0f;
        else if (g_idx1[b] == o) c = -ANTI;
        if (c != 0.f) {
            int slot = atomicAdd(&mcount, 1);
            mb[slot] = b;
            mc[slot] = c;
            xxloc += c * y[(size_t)b * OUT + o];
        }
        __syncthreads();
        const int n = mcount;
        for (int m = 0; m < n; m++) {
            const float* xr = x + (size_t)mb[m] * IN_F;
            const float cm = mc[m];
            #pragma unroll 4
            for (int i = tid; i < IN_F; i += 256)
                accum[i] = fmaf(cm, xr[i], accum[i]);
        }
        __syncthreads();
    }
    if (xxloc != 0.f) atomicAdd(&sxx, xxloc);
    __syncthreads();

    const float xx = sxx;
    float lmax = 0.f;
    #pragma unroll 4
    for (int i = tid; i < IN_F; i += 256) {
        float d = accum[i] - xx * w[(size_t)o * IN_F + i];
        g_ds[(size_t)o * IN_F + i] = d;
        lmax = fmaxf(lmax, fabsf(d));
    }
    #pragma unroll
    for (int off = 16; off > 0; off >>= 1)
        lmax = fmaxf(lmax, __shfl_xor_sync(0xffffffffu, lmax, off));
    __shared__ float smax[8];
    if ((tid & 31) == 0) smax[tid >> 5] = lmax;
    __syncthreads();
    if (tid == 0) {
        float m = smax[0];
        #pragma unroll
        for (int k = 1; k < 8; k++) m = fmaxf(m, smax[k]);
        atomicMax(&g_nc, __float_as_uint(m));
    }
}

// ---------------- new_w = w + LR * ds / nc ----------------
__global__ __launch_bounds__(256)
void finalize_kernel(const float* __restrict__ w, float* __restrict__ neww, int n) {
    const float inv = LR / __uint_as_float(g_nc);
    int i = blockIdx.x * blockDim.x + threadIdx.x;
    if (i < n) neww[i] = fmaf(g_ds[i], inv, w[i]);
}

// ---------------- launch ----------------
extern "C" void kernel_launch(void* const* d_in, const int* in_sizes, int n_in,
                              void* d_out, int out_size) {
    const float* x = (const float*)d_in[0];
    const float* w = (const float*)d_in[1];
    if (n_in >= 2 && in_sizes[0] == OUT_F * IN_F && in_sizes[1] == BATCH * IN_F) {
        w = (const float*)d_in[0];
        x = (const float*)d_in[1];
    }

    float* y_out = (float*)d_out;                       // [BATCH, OUT_F]
    float* w_out = y_out + (size_t)BATCH * OUT_F;       // [OUT_F, IN_F]

    float *xhi, *xlo, *whi, *wlo;
    cudaGetSymbolAddress((void**)&xhi, g_xhi);
    cudaGetSymbolAddress((void**)&xlo, g_xlo);
    cudaGetSymbolAddress((void**)&whi, g_whi);
    cudaGetSymbolAddress((void**)&wlo, g_wlo);

    // 0) tf32 splits
    {
        int n4x = BATCH * IN_F / 4;
        split_kernel<<<(n4x + 255) / 256, 256>>>((const float4*)x, (float4*)xhi, (float4*)xlo, n4x);
        int n4w = OUT_F * IN_F / 4;
        split_kernel<<<(n4w + 255) / 256, 256>>>((const float4*)w, (float4*)whi, (float4*)wlo, n4w);
    }
    // 1) y = x @ W^T via tf32 mma.sync, 3-product split folded into K
    {
        static bool attr_set = false;
        if (!attr_set) {
            cudaFuncSetAttribute(gemm_tf32_kernel,
                                 cudaFuncAttributeMaxDynamicSharedMemorySize, SMEM_GEMM);
            attr_set = true;
        }
        dim3 grid(OUT_F / BN_T, BATCH / BM_T);
        gemm_tf32_kernel<<<grid, 256, SMEM_GEMM>>>(xhi, xlo, whi, wlo, y_out);
    }
    // 2) top-2 per batch row (+ nc reset)
    top2_kernel<<<BATCH, 256>>>(y_out, OUT_F);
    // 3) ds + global max
    update_kernel<<<OUT_F, 256>>>(x, w, y_out, BATCH, OUT_F);
    // 4) finalize
    {
        int n = OUT_F * IN_F;
        finalize_kernel<<<(n + 255) / 256, 256>>>(w, w_out, n);
    }
}

// round 7
// speedup vs baseline: 2.0162x; 1.6606x over previous
#include <cuda_runtime.h>
#include <cuda_bf16.h>
#include <math_constants.h>
#include <cstdint>

// Problem constants
#define IN_F   1024
#define OUT_F  2048
#define BATCH  8192
#define LR     0.02f
#define ANTI   0.4f
#define PREC   1e-30f

// ---------------- scratch (no allocations allowed) ----------------
__device__ float          g_ds[(size_t)OUT_F * IN_F];
__device__ int            g_idx0[BATCH];
__device__ int            g_idx1[BATCH];
__device__ unsigned int   g_nc;
// bf16 split matrices
__device__ __nv_bfloat16  g_xhi[(size_t)BATCH * IN_F];
__device__ __nv_bfloat16  g_xlo[(size_t)BATCH * IN_F];
__device__ __nv_bfloat16  g_whi[(size_t)OUT_F * IN_F];
__device__ __nv_bfloat16  g_wlo[(size_t)OUT_F * IN_F];

// ================= helpers =================
__device__ __forceinline__ uint32_t smem_u32(const void* p) {
    uint32_t a;
    asm("{ .reg .u64 t; cvta.to.shared.u64 t, %1; cvt.u32.u64 %0, t; }" : "=r"(a) : "l"(p));
    return a;
}
__device__ __forceinline__ void cp16(uint32_t sm, const void* g) {
    asm volatile("cp.async.cg.shared.global [%0], [%1], 16;" :: "r"(sm), "l"(g) : "memory");
}
__device__ __forceinline__ void cp_commit() {
    asm volatile("cp.async.commit_group;" ::: "memory");
}
template <int N>
__device__ __forceinline__ void cp_wait() {
    asm volatile("cp.async.wait_group %0;" :: "n"(N) : "memory");
}
__device__ __forceinline__ void mma_bf16(float* d, const uint32_t* a, const uint32_t* b) {
    asm volatile(
        "mma.sync.aligned.m16n8k16.row.col.f32.bf16.bf16.f32 "
        "{%0,%1,%2,%3}, {%4,%5,%6,%7}, {%8,%9}, {%0,%1,%2,%3};"
        : "+f"(d[0]), "+f"(d[1]), "+f"(d[2]), "+f"(d[3])
        : "r"(a[0]), "r"(a[1]), "r"(a[2]), "r"(a[3]), "r"(b[0]), "r"(b[1]));
}
__device__ __forceinline__ uint32_t lds32(uint32_t p) {
    uint32_t v; asm volatile("ld.shared.b32 %0, [%1];" : "=r"(v) : "r"(p)); return v;
}

// ================= split kernel: v -> (bf16 hi, bf16 lo) =================
__global__ __launch_bounds__(256)
void split_bf16_kernel(const float4* __restrict__ src, uint2* __restrict__ hi,
                       uint2* __restrict__ lo, int n4) {
    int i = blockIdx.x * blockDim.x + threadIdx.x;
    if (i >= n4) return;
    float4 v = src[i];
    __nv_bfloat16 h0 = __float2bfloat16(v.x);
    __nv_bfloat16 h1 = __float2bfloat16(v.y);
    __nv_bfloat16 h2 = __float2bfloat16(v.z);
    __nv_bfloat16 h3 = __float2bfloat16(v.w);
    __nv_bfloat16 l0 = __float2bfloat16(v.x - __bfloat162float(h0));
    __nv_bfloat16 l1 = __float2bfloat16(v.y - __bfloat162float(h1));
    __nv_bfloat16 l2 = __float2bfloat16(v.z - __bfloat162float(h2));
    __nv_bfloat16 l3 = __float2bfloat16(v.w - __bfloat162float(h3));
    __nv_bfloat162 hp0 = __halves2bfloat162(h0, h1);
    __nv_bfloat162 hp1 = __halves2bfloat162(h2, h3);
    __nv_bfloat162 lp0 = __halves2bfloat162(l0, l1);
    __nv_bfloat162 lp1 = __halves2bfloat162(l2, l3);
    uint2 hv, lv;
    hv.x = *reinterpret_cast<uint32_t*>(&hp0); hv.y = *reinterpret_cast<uint32_t*>(&hp1);
    lv.x = *reinterpret_cast<uint32_t*>(&lp0); lv.y = *reinterpret_cast<uint32_t*>(&lp1);
    hi[i] = hv; lo[i] = lv;
}

// ================= bf16 mma.sync GEMM (3-product split folded into K) =====
// C[8192,2048] = X[8192,1024] @ W[2048,1024]^T
// Virtual K = 3*1024: region 0: xhi*whi, region 1: xlo*whi, region 2: xhi*wlo.
#define BM_T 128
#define BN_T 256
#define ROWB 144u             // padded row bytes (128 data + 16 pad): bank stride 4
#define STAGE_B ((BM_T + BN_T) * ROWB)   // 384*144 = 55296
#define NSTAGEG 3
#define NCHUNKG 48            // 3 regions * 16 chunks
#define SMEM_GEMM (NSTAGEG * STAGE_B)    // 165888

__global__ __launch_bounds__(256, 1)
void gemm_bf16_kernel(const __nv_bfloat16* __restrict__ Xhi,
                      const __nv_bfloat16* __restrict__ Xlo,
                      const __nv_bfloat16* __restrict__ Whi,
                      const __nv_bfloat16* __restrict__ Wlo,
                      float* __restrict__ C) {
    extern __shared__ char smem[];
    const uint32_t sb = smem_u32(smem);
    const int tid  = threadIdx.x;
    const int wid  = tid >> 5;
    const int lane = tid & 31;
    const int gr   = lane >> 2;    // 0..7
    const int tig  = lane & 3;     // 0..3
    const int wm   = wid & 1;      // 2 warp rows (64 each)
    const int wn   = wid >> 1;     // 4 warp cols (64 each)
    const int m0 = blockIdx.y * BM_T;
    const int n0 = blockIdx.x * BN_T;

    auto issue_chunk = [&](int s) {
        const int region = s >> 4;             // 16 chunks per region
        const int kb = (s & 15) * 128;         // byte offset into K (64 elts * 2B)
        const __nv_bfloat16* Asrc = (region == 1) ? Xlo : Xhi;
        const __nv_bfloat16* Bsrc = (region == 2) ? Wlo : Whi;
        const uint32_t base = sb + (uint32_t)(s % NSTAGEG) * STAGE_B;
        #pragma unroll
        for (int c = 0; c < 12; c++) {
            int idx = tid + c * 256;           // 0..3071
            int row = idx >> 3;                // 0..383
            int g   = idx & 7;                 // 16B granule in 128B row
            const char* gp;
            if (row < BM_T)
                gp = (const char*)Asrc + (size_t)(m0 + row) * (IN_F * 2) + kb + g * 16;
            else
                gp = (const char*)Bsrc + (size_t)(n0 + row - BM_T) * (IN_F * 2) + kb + g * 16;
            cp16(base + row * ROWB + g * 16, gp);
        }
        cp_commit();
    };

    float acc[4][8][4];
    #pragma unroll
    for (int i = 0; i < 4; i++)
        #pragma unroll
        for (int j = 0; j < 8; j++)
            #pragma unroll
            for (int r = 0; r < 4; r++) acc[i][j][r] = 0.f;

    issue_chunk(0);
    issue_chunk(1);

    for (int s = 0; s < NCHUNKG; s++) {
        if (s == NCHUNKG - 1) cp_wait<0>(); else cp_wait<1>();
        __syncthreads();

        const uint32_t base = sb + (uint32_t)(s % NSTAGEG) * STAGE_B;
        const uint32_t aB = base;
        const uint32_t bB = base + BM_T * ROWB;

        #pragma unroll
        for (int ks = 0; ks < 4; ks++) {
            const uint32_t k0b = ks * 32;      // 16 elts * 2B
            uint32_t a[4][4], b[8][2];
            #pragma unroll
            for (int i = 0; i < 4; i++) {
                uint32_t r0 = aB + (uint32_t)(wm * 64 + i * 16 + gr) * ROWB + k0b + tig * 4;
                uint32_t r1 = r0 + 8 * ROWB;
                a[i][0] = lds32(r0);
                a[i][1] = lds32(r1);
                a[i][2] = lds32(r0 + 16);
                a[i][3] = lds32(r1 + 16);
            }
            #pragma unroll
            for (int j = 0; j < 8; j++) {
                uint32_t p = bB + (uint32_t)(wn * 64 + j * 8 + gr) * ROWB + k0b + tig * 4;
                b[j][0] = lds32(p);
                b[j][1] = lds32(p + 16);
            }
            #pragma unroll
            for (int i = 0; i < 4; i++)
                #pragma unroll
                for (int j = 0; j < 8; j++)
                    mma_bf16(acc[i][j], a[i], b[j]);
        }
        __syncthreads();
        if (s + 2 < NCHUNKG) issue_chunk(s + 2);
    }

    // writeback
    #pragma unroll
    for (int i = 0; i < 4; i++) {
        int r0 = m0 + wm * 64 + i * 16 + gr;
        #pragma unroll
        for (int j = 0; j < 8; j++) {
            int cc = n0 + wn * 64 + j * 8 + 2 * tig;
            *reinterpret_cast<float2*>(C + (size_t)r0 * OUT_F + cc) =
                make_float2(acc[i][j][0], acc[i][j][1]);
            *reinterpret_cast<float2*>(C + (size_t)(r0 + 8) * OUT_F + cc) =
                make_float2(acc[i][j][2], acc[i][j][3]);
        }
    }
}

// ---------------- Top-2 per batch row of y [BATCH, OUT_F] ----------------
__device__ __forceinline__ void merge_top2(float& av1, int& ai1, float& av2, int& ai2,
                                           float bv1, int bi1, float bv2, int bi2) {
    if (bv1 > av1 || (bv1 == av1 && bi1 < ai1)) {
        float nv2; int ni2;
        if (av1 > bv2 || (av1 == bv2 && ai1 < bi2)) { nv2 = av1; ni2 = ai1; }
        else                                         { nv2 = bv2; ni2 = bi2; }
        av1 = bv1; ai1 = bi1; av2 = nv2; ai2 = ni2;
    } else {
        if (bv1 > av2 || (bv1 == av2 && bi1 < ai2)) { av2 = bv1; ai2 = bi1; }
    }
}

__global__ __launch_bounds__(256)
void top2_kernel(const float* __restrict__ y, int N) {
    const int b   = blockIdx.x;
    const int tid = threadIdx.x;
    if (b == 0 && tid == 0) g_nc = __float_as_uint(PREC);

    const float* row = y + (size_t)b * N;
    float v1 = -CUDART_INF_F, v2 = -CUDART_INF_F;
    int   i1 = 0x7fffffff,    i2 = 0x7fffffff;
    for (int j = tid; j < N; j += 256) {
        float v = row[j];
        if (v > v1) { v2 = v1; i2 = i1; v1 = v; i1 = j; }
        else if (v > v2) { v2 = v; i2 = j; }
    }

    __shared__ float sv1[256], sv2[256];
    __shared__ int   si1[256], si2[256];
    sv1[tid] = v1; si1[tid] = i1; sv2[tid] = v2; si2[tid] = i2;
    __syncthreads();
    for (int s = 128; s > 0; s >>= 1) {
        if (tid < s) {
            float av1 = sv1[tid], av2 = sv2[tid];
            int   ai1 = si1[tid], ai2 = si2[tid];
            merge_top2(av1, ai1, av2, ai2, sv1[tid + s], si1[tid + s], sv2[tid + s], si2[tid + s]);
            sv1[tid] = av1; si1[tid] = ai1; sv2[tid] = av2; si2[tid] = ai2;
        }
        __syncthreads();
    }
    if (tid == 0) { g_idx0[b] = si1[0]; g_idx1[b] = si2[0]; }
}

// ---------------- ds = yl@x - xx*W, and nc = max|ds| ----------------
#define CHUNK 256
__global__ __launch_bounds__(256)
void update_kernel(const float* __restrict__ x, const float* __restrict__ w,
                   const float* __restrict__ y, int B, int OUT) {
    const int o   = blockIdx.x;
    const int tid = threadIdx.x;

    __shared__ float accum[IN_F];
    __shared__ int   mb[CHUNK];
    __shared__ float mc[CHUNK];
    __shared__ int   mcount;
    __shared__ float sxx;

    for (int i = tid; i < IN_F; i += 256) accum[i] = 0.f;
    if (tid == 0) sxx = 0.f;
    __syncthreads();

    float xxloc = 0.f;
    for (int b0 = 0; b0 < B; b0 += CHUNK) {
        if (tid == 0) mcount = 0;
        __syncthreads();
        int b = b0 + tid;
        float c = 0.f;
        if (g_idx0[b] == o)      c = 1.0f;
        else if (g_idx1[b] == o) c = -ANTI;
        if (c != 0.f) {
            int slot = atomicAdd(&mcount, 1);
            mb[slot] = b;
            mc[slot] = c;
            xxloc += c * y[(size_t)b * OUT + o];
        }
        __syncthreads();
        const int n = mcount;
        for (int m = 0; m < n; m++) {
            const float* xr = x + (size_t)mb[m] * IN_F;
            const float cm = mc[m];
            #pragma unroll 4
            for (int i = tid; i < IN_F; i += 256)
                accum[i] = fmaf(cm, xr[i], accum[i]);
        }
        __syncthreads();
    }
    if (xxloc != 0.f) atomicAdd(&sxx, xxloc);
    __syncthreads();

    const float xx = sxx;
    float lmax = 0.f;
    #pragma unroll 4
    for (int i = tid; i < IN_F; i += 256) {
        float d = accum[i] - xx * w[(size_t)o * IN_F + i];
        g_ds[(size_t)o * IN_F + i] = d;
        lmax = fmaxf(lmax, fabsf(d));
    }
    #pragma unroll
    for (int off = 16; off > 0; off >>= 1)
        lmax = fmaxf(lmax, __shfl_xor_sync(0xffffffffu, lmax, off));
    __shared__ float smax[8];
    if ((tid & 31) == 0) smax[tid >> 5] = lmax;
    __syncthreads();
    if (tid == 0) {
        float m = smax[0];
        #pragma unroll
        for (int k = 1; k < 8; k++) m = fmaxf(m, smax[k]);
        atomicMax(&g_nc, __float_as_uint(m));
    }
}

// ---------------- new_w = w + LR * ds / nc ----------------
__global__ __launch_bounds__(256)
void finalize_kernel(const float* __restrict__ w, float* __restrict__ neww, int n) {
    const float inv = LR / __uint_as_float(g_nc);
    int i = blockIdx.x * blockDim.x + threadIdx.x;
    if (i < n) neww[i] = fmaf(g_ds[i], inv, w[i]);
}

// ---------------- launch ----------------
extern "C" void kernel_launch(void* const* d_in, const int* in_sizes, int n_in,
                              void* d_out, int out_size) {
    const float* x = (const float*)d_in[0];
    const float* w = (const float*)d_in[1];
    if (n_in >= 2 && in_sizes[0] == OUT_F * IN_F && in_sizes[1] == BATCH * IN_F) {
        w = (const float*)d_in[0];
        x = (const float*)d_in[1];
    }

    float* y_out = (float*)d_out;                       // [BATCH, OUT_F]
    float* w_out = y_out + (size_t)BATCH * OUT_F;       // [OUT_F, IN_F]

    __nv_bfloat16 *xhi, *xlo, *whi, *wlo;
    cudaGetSymbolAddress((void**)&xhi, g_xhi);
    cudaGetSymbolAddress((void**)&xlo, g_xlo);
    cudaGetSymbolAddress((void**)&whi, g_whi);
    cudaGetSymbolAddress((void**)&wlo, g_wlo);

    // 0) bf16 splits
    {
        int n4x = BATCH * IN_F / 4;
        split_bf16_kernel<<<(n4x + 255) / 256, 256>>>((const float4*)x, (uint2*)xhi, (uint2*)xlo, n4x);
        int n4w = OUT_F * IN_F / 4;
        split_bf16_kernel<<<(n4w + 255) / 256, 256>>>((const float4*)w, (uint2*)whi, (uint2*)wlo, n4w);
    }
    // 1) y = x @ W^T via bf16 mma.sync, 3-product split folded into K
    {
        cudaFuncSetAttribute(gemm_bf16_kernel,
                             cudaFuncAttributeMaxDynamicSharedMemorySize, SMEM_GEMM);
        dim3 grid(OUT_F / BN_T, BATCH / BM_T);
        gemm_bf16_kernel<<<grid, 256, SMEM_GEMM>>>(xhi, xlo, whi, wlo, y_out);
    }
    // 2) top-2 per batch row (+ nc reset)
    top2_kernel<<<BATCH, 256>>>(y_out, OUT_F);
    // 3) ds + global max
    update_kernel<<<OUT_F, 256>>>(x, w, y_out, BATCH, OUT_F);
    // 4) finalize
    {
        int n = OUT_F * IN_F;
        finalize_kernel<<<(n + 255) / 256, 256>>>(w, w_out, n);
    }
}

// round 8
// speedup vs baseline: 2.1221x; 1.0525x over previous
#include <cuda_runtime.h>
#include <cuda_bf16.h>
#include <math_constants.h>
#include <cstdint>

// Problem constants
#define IN_F   1024
#define OUT_F  2048
#define BATCH  8192
#define LR     0.02f
#define ANTI   0.4f
#define PREC   1e-30f

// ---------------- scratch (no allocations allowed) ----------------
__device__ float          g_ds[(size_t)OUT_F * IN_F];
__device__ int            g_idx0[BATCH];
__device__ int            g_idx1[BATCH];
__device__ unsigned int   g_nc;
// bf16 split matrices
__device__ __nv_bfloat16  g_xhi[(size_t)BATCH * IN_F];
__device__ __nv_bfloat16  g_xlo[(size_t)BATCH * IN_F];
__device__ __nv_bfloat16  g_whi[(size_t)OUT_F * IN_F];
__device__ __nv_bfloat16  g_wlo[(size_t)OUT_F * IN_F];

// ================= helpers =================
__device__ __forceinline__ uint32_t smem_u32(const void* p) {
    uint32_t a;
    asm("{ .reg .u64 t; cvta.to.shared.u64 t, %1; cvt.u32.u64 %0, t; }" : "=r"(a) : "l"(p));
    return a;
}
__device__ __forceinline__ void cp16(uint32_t sm, const void* g) {
    asm volatile("cp.async.cg.shared.global [%0], [%1], 16;" :: "r"(sm), "l"(g) : "memory");
}
__device__ __forceinline__ void cp_commit() {
    asm volatile("cp.async.commit_group;" ::: "memory");
}
template <int N>
__device__ __forceinline__ void cp_wait() {
    asm volatile("cp.async.wait_group %0;" :: "n"(N) : "memory");
}
__device__ __forceinline__ void mma_bf16(float* d, const uint32_t* a, const uint32_t* b) {
    asm volatile(
        "mma.sync.aligned.m16n8k16.row.col.f32.bf16.bf16.f32 "
        "{%0,%1,%2,%3}, {%4,%5,%6,%7}, {%8,%9}, {%0,%1,%2,%3};"
        : "+f"(d[0]), "+f"(d[1]), "+f"(d[2]), "+f"(d[3])
        : "r"(a[0]), "r"(a[1]), "r"(a[2]), "r"(a[3]), "r"(b[0]), "r"(b[1]));
}
__device__ __forceinline__ void ldsm4(uint32_t& r0, uint32_t& r1, uint32_t& r2, uint32_t& r3,
                                      uint32_t addr) {
    asm volatile("ldmatrix.sync.aligned.m8n8.x4.shared.b16 {%0,%1,%2,%3}, [%4];"
                 : "=r"(r0), "=r"(r1), "=r"(r2), "=r"(r3) : "r"(addr));
}

// ================= split kernel: v -> (bf16 hi, bf16 lo) =================
__global__ __launch_bounds__(256)
void split_bf16_kernel(const float4* __restrict__ src, uint2* __restrict__ hi,
                       uint2* __restrict__ lo, int n4) {
    int i = blockIdx.x * blockDim.x + threadIdx.x;
    if (i >= n4) return;
    float4 v = src[i];
    __nv_bfloat16 h0 = __float2bfloat16(v.x);
    __nv_bfloat16 h1 = __float2bfloat16(v.y);
    __nv_bfloat16 h2 = __float2bfloat16(v.z);
    __nv_bfloat16 h3 = __float2bfloat16(v.w);
    __nv_bfloat16 l0 = __float2bfloat16(v.x - __bfloat162float(h0));
    __nv_bfloat16 l1 = __float2bfloat16(v.y - __bfloat162float(h1));
    __nv_bfloat16 l2 = __float2bfloat16(v.z - __bfloat162float(h2));
    __nv_bfloat16 l3 = __float2bfloat16(v.w - __bfloat162float(h3));
    __nv_bfloat162 hp0 = __halves2bfloat162(h0, h1);
    __nv_bfloat162 hp1 = __halves2bfloat162(h2, h3);
    __nv_bfloat162 lp0 = __halves2bfloat162(l0, l1);
    __nv_bfloat162 lp1 = __halves2bfloat162(l2, l3);
    uint2 hv, lv;
    hv.x = *reinterpret_cast<uint32_t*>(&hp0); hv.y = *reinterpret_cast<uint32_t*>(&hp1);
    lv.x = *reinterpret_cast<uint32_t*>(&lp0); lv.y = *reinterpret_cast<uint32_t*>(&lp1);
    hi[i] = hv; lo[i] = lv;
}

// ================= bf16 mma.sync GEMM (3-product split folded into K) =====
// C[8192,2048] = X[8192,1024] @ W[2048,1024]^T
// Virtual K = 3*1024: region 0: xhi*whi, region 1: xlo*whi, region 2: xhi*wlo.
#define BM_T 128
#define BN_T 256
#define ROWB 144u             // padded row bytes (128 data + 16 pad): bank stride 4
#define STAGE_B ((BM_T + BN_T) * ROWB)   // 384*144 = 55296
#define NSTAGEG 3
#define NCHUNKG 48            // 3 regions * 16 chunks
#define SMEM_GEMM (NSTAGEG * STAGE_B)    // 165888

__global__ __launch_bounds__(256, 1)
void gemm_bf16_kernel(const __nv_bfloat16* __restrict__ Xhi,
                      const __nv_bfloat16* __restrict__ Xlo,
                      const __nv_bfloat16* __restrict__ Whi,
                      const __nv_bfloat16* __restrict__ Wlo,
                      float* __restrict__ C) {
    extern __shared__ char smem[];
    const uint32_t sb = smem_u32(smem);
    const int tid  = threadIdx.x;
    const int wid  = tid >> 5;
    const int lane = tid & 31;
    const int gr   = lane >> 2;    // 0..7
    const int tig  = lane & 3;     // 0..3
    const int wm   = wid & 1;      // 2 warp rows (64 each)
    const int wn   = wid >> 1;     // 4 warp cols (64 each)
    const int m0 = blockIdx.y * BM_T;
    const int n0 = blockIdx.x * BN_T;

    // ldmatrix per-lane base offsets (within A / B regions of a stage)
    // A tiles (16x16 per i): lanes 0..15 -> rows (lane&15), k-half by lane>>4
    const uint32_t aoff = (uint32_t)(wm * 64 + (lane & 15)) * ROWB + (uint32_t)(lane >> 4) * 16;
    // B tiles (two 8-col j's per ldsm4): row = (lane>>4)*8 + (lane&7), k-half (lane>>3)&1
    const uint32_t boff = (uint32_t)(wn * 64 + ((lane >> 4) * 8) + (lane & 7)) * ROWB
                        + (uint32_t)((lane >> 3) & 1) * 16;

    auto issue_chunk = [&](int s) {
        const int region = s >> 4;             // 16 chunks per region
        const int kb = (s & 15) * 128;         // byte offset into K (64 elts * 2B)
        const __nv_bfloat16* Asrc = (region == 1) ? Xlo : Xhi;
        const __nv_bfloat16* Bsrc = (region == 2) ? Wlo : Whi;
        const uint32_t base = sb + (uint32_t)(s % NSTAGEG) * STAGE_B;
        #pragma unroll
        for (int c = 0; c < 12; c++) {
            int idx = tid + c * 256;           // 0..3071
            int row = idx >> 3;                // 0..383
            int g   = idx & 7;                 // 16B granule in 128B row
            const char* gp;
            if (row < BM_T)
                gp = (const char*)Asrc + (size_t)(m0 + row) * (IN_F * 2) + kb + g * 16;
            else
                gp = (const char*)Bsrc + (size_t)(n0 + row - BM_T) * (IN_F * 2) + kb + g * 16;
            cp16(base + row * ROWB + g * 16, gp);
        }
        cp_commit();
    };

    float acc[4][8][4];
    #pragma unroll
    for (int i = 0; i < 4; i++)
        #pragma unroll
        for (int j = 0; j < 8; j++)
            #pragma unroll
            for (int r = 0; r < 4; r++) acc[i][j][r] = 0.f;

    issue_chunk(0);
    issue_chunk(1);

    for (int s = 0; s < NCHUNKG; s++) {
        if (s == NCHUNKG - 1) cp_wait<0>(); else cp_wait<1>();
        __syncthreads();
        // refill early: stage (s+2)%3 was fully consumed before the barrier above
        if (s + 2 < NCHUNKG) issue_chunk(s + 2);

        const uint32_t base = sb + (uint32_t)(s % NSTAGEG) * STAGE_B;
        const uint32_t aB = base + aoff;
        const uint32_t bB = base + BM_T * ROWB + boff;

        #pragma unroll
        for (int ks = 0; ks < 4; ks++) {
            const uint32_t k0b = ks * 32;      // 16 elts * 2B
            uint32_t a[4][4], b[8][2];
            #pragma unroll
            for (int i = 0; i < 4; i++)
                ldsm4(a[i][0], a[i][1], a[i][2], a[i][3], aB + (uint32_t)i * (16 * ROWB) + k0b);
            #pragma unroll
            for (int jj = 0; jj < 4; jj++)
                ldsm4(b[2*jj][0], b[2*jj][1], b[2*jj+1][0], b[2*jj+1][1],
                      bB + (uint32_t)jj * (16 * ROWB) + k0b);
            #pragma unroll
            for (int i = 0; i < 4; i++)
                #pragma unroll
                for (int j = 0; j < 8; j++)
                    mma_bf16(acc[i][j], a[i], b[j]);
        }
        // no trailing barrier: next iteration's barrier orders stage reuse
    }

    // writeback
    #pragma unroll
    for (int i = 0; i < 4; i++) {
        int r0 = m0 + wm * 64 + i * 16 + gr;
        #pragma unroll
        for (int j = 0; j < 8; j++) {
            int cc = n0 + wn * 64 + j * 8 + 2 * tig;
            *reinterpret_cast<float2*>(C + (size_t)r0 * OUT_F + cc) =
                make_float2(acc[i][j][0], acc[i][j][1]);
            *reinterpret_cast<float2*>(C + (size_t)(r0 + 8) * OUT_F + cc) =
                make_float2(acc[i][j][2], acc[i][j][3]);
        }
    }
}

// ---------------- Top-2 per batch row of y [BATCH, OUT_F] ----------------
__device__ __forceinline__ void merge_top2(float& av1, int& ai1, float& av2, int& ai2,
                                           float bv1, int bi1, float bv2, int bi2) {
    if (bv1 > av1 || (bv1 == av1 && bi1 < ai1)) {
        float nv2; int ni2;
        if (av1 > bv2 || (av1 == bv2 && ai1 < bi2)) { nv2 = av1; ni2 = ai1; }
        else                                         { nv2 = bv2; ni2 = bi2; }
        av1 = bv1; ai1 = bi1; av2 = nv2; ai2 = ni2;
    } else {
        if (bv1 > av2 || (bv1 == av2 && bi1 < ai2)) { av2 = bv1; ai2 = bi1; }
    }
}

__global__ __launch_bounds__(256)
void top2_kernel(const float* __restrict__ y, int N) {
    const int b   = blockIdx.x;
    const int tid = threadIdx.x;
    if (b == 0 && tid == 0) g_nc = __float_as_uint(PREC);

    const float4* row4 = reinterpret_cast<const float4*>(y + (size_t)b * N);
    float v1 = -CUDART_INF_F, v2 = -CUDART_INF_F;
    int   i1 = 0x7fffffff,    i2 = 0x7fffffff;

    auto upd = [&](float v, int j) {
        if (v > v1) { v2 = v1; i2 = i1; v1 = v; i1 = j; }
        else if (v > v2) { v2 = v; i2 = j; }
    };
    #pragma unroll
    for (int it = 0; it < 2; it++) {
        int j4 = tid + it * 256;           // N/4 = 512 float4s
        float4 v = row4[j4];
        int jb = 4 * j4;
        upd(v.x, jb); upd(v.y, jb + 1); upd(v.z, jb + 2); upd(v.w, jb + 3);
    }

    __shared__ float sv1[256], sv2[256];
    __shared__ int   si1[256], si2[256];
    sv1[tid] = v1; si1[tid] = i1; sv2[tid] = v2; si2[tid] = i2;
    __syncthreads();
    for (int s = 128; s > 0; s >>= 1) {
        if (tid < s) {
            float av1 = sv1[tid], av2 = sv2[tid];
            int   ai1 = si1[tid], ai2 = si2[tid];
            merge_top2(av1, ai1, av2, ai2, sv1[tid + s], si1[tid + s], sv2[tid + s], si2[tid + s]);
            sv1[tid] = av1; si1[tid] = ai1; sv2[tid] = av2; si2[tid] = ai2;
        }
        __syncthreads();
    }
    if (tid == 0) { g_idx0[b] = si1[0]; g_idx1[b] = si2[0]; }
}

// ---------------- ds = yl@x - xx*W, and nc = max|ds| ----------------
// One block per output unit o. Thread t owns columns 4t..4t+3 in registers.
#define CHUNK 256
__global__ __launch_bounds__(256)
void update_kernel(const float* __restrict__ x, const float* __restrict__ w,
                   const float* __restrict__ y, int B, int OUT) {
    const int o   = blockIdx.x;
    const int tid = threadIdx.x;

    __shared__ int   mb[CHUNK];
    __shared__ float mc[CHUNK];
    __shared__ int   mcount;
    __shared__ float sxx;

    float4 acc = make_float4(0.f, 0.f, 0.f, 0.f);
    if (tid == 0) sxx = 0.f;
    __syncthreads();

    float xxloc = 0.f;
    for (int b0 = 0; b0 < B; b0 += CHUNK) {
        if (tid == 0) mcount = 0;
        __syncthreads();
        int b = b0 + tid;
        float c = 0.f;
        if (g_idx0[b] == o)      c = 1.0f;
        else if (g_idx1[b] == o) c = -ANTI;
        if (c != 0.f) {
            int slot = atomicAdd(&mcount, 1);
            mb[slot] = b;
            mc[slot] = c;
            xxloc += c * y[(size_t)b * OUT + o];
        }
        __syncthreads();
        const int n = mcount;
        for (int m = 0; m < n; m++) {
            const float4* xr4 = reinterpret_cast<const float4*>(x + (size_t)mb[m] * IN_F);
            const float cm = mc[m];
            float4 xv = xr4[tid];
            acc.x = fmaf(cm, xv.x, acc.x);
            acc.y = fmaf(cm, xv.y, acc.y);
            acc.z = fmaf(cm, xv.z, acc.z);
            acc.w = fmaf(cm, xv.w, acc.w);
        }
        __syncthreads();
    }
    if (xxloc != 0.f) atomicAdd(&sxx, xxloc);
    __syncthreads();

    const float xx = sxx;
    const float4* w4 = reinterpret_cast<const float4*>(w + (size_t)o * IN_F);
    float4 wv = w4[tid];
    float4 d;
    d.x = acc.x - xx * wv.x;
    d.y = acc.y - xx * wv.y;
    d.z = acc.z - xx * wv.z;
    d.w = acc.w - xx * wv.w;
    reinterpret_cast<float4*>(g_ds + (size_t)o * IN_F)[tid] = d;

    float lmax = fmaxf(fmaxf(fabsf(d.x), fabsf(d.y)), fmaxf(fabsf(d.z), fabsf(d.w)));
    #pragma unroll
    for (int off = 16; off > 0; off >>= 1)
        lmax = fmaxf(lmax, __shfl_xor_sync(0xffffffffu, lmax, off));
    __shared__ float smax[8];
    if ((tid & 31) == 0) smax[tid >> 5] = lmax;
    __syncthreads();
    if (tid == 0) {
        float m = smax[0];
        #pragma unroll
        for (int k = 1; k < 8; k++) m = fmaxf(m, smax[k]);
        atomicMax(&g_nc, __float_as_uint(m));
    }
}

// ---------------- new_w = w + LR * ds / nc ----------------
__global__ __launch_bounds__(256)
void finalize_kernel(const float4* __restrict__ w4, float4* __restrict__ neww4, int n4) {
    const float inv = LR / __uint_as_float(g_nc);
    int i = blockIdx.x * blockDim.x + threadIdx.x;
    if (i < n4) {
        const float4* ds4 = reinterpret_cast<const float4*>(g_ds);
        float4 d = ds4[i];
        float4 v = w4[i];
        v.x = fmaf(d.x, inv, v.x);
        v.y = fmaf(d.y, inv, v.y);
        v.z = fmaf(d.z, inv, v.z);
        v.w = fmaf(d.w, inv, v.w);
        neww4[i] = v;
    }
}

// ---------------- launch ----------------
extern "C" void kernel_launch(void* const* d_in, const int* in_sizes, int n_in,
                              void* d_out, int out_size) {
    const float* x = (const float*)d_in[0];
    const float* w = (const float*)d_in[1];
    if (n_in >= 2 && in_sizes[0] == OUT_F * IN_F && in_sizes[1] == BATCH * IN_F) {
        w = (const float*)d_in[0];
        x = (const float*)d_in[1];
    }

    float* y_out = (float*)d_out;                       // [BATCH, OUT_F]
    float* w_out = y_out + (size_t)BATCH * OUT_F;       // [OUT_F, IN_F]

    __nv_bfloat16 *xhi, *xlo, *whi, *wlo;
    cudaGetSymbolAddress((void**)&xhi, g_xhi);
    cudaGetSymbolAddress((void**)&xlo, g_xlo);
    cudaGetSymbolAddress((void**)&whi, g_whi);
    cudaGetSymbolAddress((void**)&wlo, g_wlo);

    // 0) bf16 splits
    {
        int n4x = BATCH * IN_F / 4;
        split_bf16_kernel<<<(n4x + 255) / 256, 256>>>((const float4*)x, (uint2*)xhi, (uint2*)xlo, n4x);
        int n4w = OUT_F * IN_F / 4;
        split_bf16_kernel<<<(n4w + 255) / 256, 256>>>((const float4*)w, (uint2*)whi, (uint2*)wlo, n4w);
    }
    // 1) y = x @ W^T via bf16 mma.sync, 3-product split folded into K
    {
        cudaFuncSetAttribute(gemm_bf16_kernel,
                             cudaFuncAttributeMaxDynamicSharedMemorySize, SMEM_GEMM);
        dim3 grid(OUT_F / BN_T, BATCH / BM_T);
        gemm_bf16_kernel<<<grid, 256, SMEM_GEMM>>>(xhi, xlo, whi, wlo, y_out);
    }
    // 2) top-2 per batch row (+ nc reset)
    top2_kernel<<<BATCH, 256>>>(y_out, OUT_F);
    // 3) ds + global max
    update_kernel<<<OUT_F, 256>>>(x, w, y_out, BATCH, OUT_F);
    // 4) finalize
    {
        int n4 = OUT_F * IN_F / 4;
        finalize_kernel<<<(n4 + 255) / 256, 256>>>((const float4*)w, (float4*)w_out, n4);
    }
}

// round 9
// speedup vs baseline: 2.1732x; 1.0241x over previous
#include <cuda_runtime.h>
#include <cuda_bf16.h>
#include <math_constants.h>
#include <cstdint>

// Problem constants
#define IN_F   1024
#define OUT_F  2048
#define BATCH  8192
#define LR     0.02f
#define ANTI   0.4f
#define PREC   1e-30f

// ---------------- scratch (no allocations allowed) ----------------
__device__ float          g_ds[(size_t)OUT_F * IN_F];
__device__ int            g_idx0[BATCH];
__device__ int            g_idx1[BATCH];
__device__ unsigned int   g_nc;
// bf16 split matrices
__device__ __nv_bfloat16  g_xhi[(size_t)BATCH * IN_F];
__device__ __nv_bfloat16  g_xlo[(size_t)BATCH * IN_F];
__device__ __nv_bfloat16  g_whi[(size_t)OUT_F * IN_F];
__device__ __nv_bfloat16  g_wlo[(size_t)OUT_F * IN_F];

// ================= helpers =================
__device__ __forceinline__ uint32_t smem_u32(const void* p) {
    uint32_t a;
    asm("{ .reg .u64 t; cvta.to.shared.u64 t, %1; cvt.u32.u64 %0, t; }" : "=r"(a) : "l"(p));
    return a;
}
__device__ __forceinline__ void cp16(uint32_t sm, const void* g) {
    asm volatile("cp.async.cg.shared.global [%0], [%1], 16;" :: "r"(sm), "l"(g) : "memory");
}
__device__ __forceinline__ void cp_commit() {
    asm volatile("cp.async.commit_group;" ::: "memory");
}
template <int N>
__device__ __forceinline__ void cp_wait() {
    asm volatile("cp.async.wait_group %0;" :: "n"(N) : "memory");
}
__device__ __forceinline__ void mma_bf16(float* d, const uint32_t* a, const uint32_t* b) {
    asm volatile(
        "mma.sync.aligned.m16n8k16.row.col.f32.bf16.bf16.f32 "
        "{%0,%1,%2,%3}, {%4,%5,%6,%7}, {%8,%9}, {%0,%1,%2,%3};"
        : "+f"(d[0]), "+f"(d[1]), "+f"(d[2]), "+f"(d[3])
        : "r"(a[0]), "r"(a[1]), "r"(a[2]), "r"(a[3]), "r"(b[0]), "r"(b[1]));
}
__device__ __forceinline__ void ldsm4(uint32_t& r0, uint32_t& r1, uint32_t& r2, uint32_t& r3,
                                      uint32_t addr) {
    asm volatile("ldmatrix.sync.aligned.m8n8.x4.shared.b16 {%0,%1,%2,%3}, [%4];"
                 : "=r"(r0), "=r"(r1), "=r"(r2), "=r"(r3) : "r"(addr));
}

// ================= fused split kernel: {x,w} -> (bf16 hi, bf16 lo) =========
__global__ __launch_bounds__(256)
void split_bf16_fused(const float4* __restrict__ x4, const float4* __restrict__ w4,
                      uint2* __restrict__ xhi, uint2* __restrict__ xlo,
                      uint2* __restrict__ whi, uint2* __restrict__ wlo,
                      int n4x, int n4tot) {
    int i = blockIdx.x * blockDim.x + threadIdx.x;
    if (i == 0) g_nc = __float_as_uint(PREC);   // reset for this launch (before update)
    if (i >= n4tot) return;
    const float4* src; uint2 *hi, *lo; int idx;
    if (i < n4x) { src = x4; hi = xhi; lo = xlo; idx = i; }
    else         { src = w4; hi = whi; lo = wlo; idx = i - n4x; }
    float4 v = src[idx];
    __nv_bfloat16 h0 = __float2bfloat16(v.x);
    __nv_bfloat16 h1 = __float2bfloat16(v.y);
    __nv_bfloat16 h2 = __float2bfloat16(v.z);
    __nv_bfloat16 h3 = __float2bfloat16(v.w);
    __nv_bfloat16 l0 = __float2bfloat16(v.x - __bfloat162float(h0));
    __nv_bfloat16 l1 = __float2bfloat16(v.y - __bfloat162float(h1));
    __nv_bfloat16 l2 = __float2bfloat16(v.z - __bfloat162float(h2));
    __nv_bfloat16 l3 = __float2bfloat16(v.w - __bfloat162float(h3));
    __nv_bfloat162 hp0 = __halves2bfloat162(h0, h1);
    __nv_bfloat162 hp1 = __halves2bfloat162(h2, h3);
    __nv_bfloat162 lp0 = __halves2bfloat162(l0, l1);
    __nv_bfloat162 lp1 = __halves2bfloat162(l2, l3);
    uint2 hv, lv;
    hv.x = *reinterpret_cast<uint32_t*>(&hp0); hv.y = *reinterpret_cast<uint32_t*>(&hp1);
    lv.x = *reinterpret_cast<uint32_t*>(&lp0); lv.y = *reinterpret_cast<uint32_t*>(&lp1);
    hi[idx] = hv; lo[idx] = lv;
}

// ================= bf16 mma.sync GEMM (3-product split folded into K) =====
// C[8192,2048] = X[8192,1024] @ W[2048,1024]^T
// Virtual K = 3*1024: region 0: xhi*whi, region 1: xlo*whi, region 2: xhi*wlo.
#define BM_T 128
#define BN_T 256
#define ROWB 144u             // padded row bytes (128 data + 16 pad): bank stride 4
#define STAGE_B ((BM_T + BN_T) * ROWB)   // 384*144 = 55296
#define NSTAGEG 3
#define NCHUNKG 48            // 3 regions * 16 chunks
#define SMEM_GEMM (NSTAGEG * STAGE_B)    // 165888

__global__ __launch_bounds__(256, 1)
void gemm_bf16_kernel(const __nv_bfloat16* __restrict__ Xhi,
                      const __nv_bfloat16* __restrict__ Xlo,
                      const __nv_bfloat16* __restrict__ Whi,
                      const __nv_bfloat16* __restrict__ Wlo,
                      float* __restrict__ C) {
    extern __shared__ char smem[];
    const uint32_t sb = smem_u32(smem);
    const int tid  = threadIdx.x;
    const int wid  = tid >> 5;
    const int lane = tid & 31;
    const int gr   = lane >> 2;    // 0..7
    const int tig  = lane & 3;     // 0..3
    const int wm   = wid & 1;      // 2 warp rows (64 each)
    const int wn   = wid >> 1;     // 4 warp cols (64 each)
    const int m0 = blockIdx.y * BM_T;
    const int n0 = blockIdx.x * BN_T;

    // ldmatrix per-lane base offsets (within A / B regions of a stage)
    const uint32_t aoff = (uint32_t)(wm * 64 + (lane & 15)) * ROWB + (uint32_t)(lane >> 4) * 16;
    const uint32_t boff = (uint32_t)(wn * 64 + ((lane >> 4) * 8) + (lane & 7)) * ROWB
                        + (uint32_t)((lane >> 3) & 1) * 16;

    auto issue_chunk = [&](int s) {
        const int region = s >> 4;             // 16 chunks per region
        const int kb = (s & 15) * 128;         // byte offset into K (64 elts * 2B)
        const __nv_bfloat16* Asrc = (region == 1) ? Xlo : Xhi;
        const __nv_bfloat16* Bsrc = (region == 2) ? Wlo : Whi;
        const uint32_t base = sb + (uint32_t)(s % NSTAGEG) * STAGE_B;
        #pragma unroll
        for (int c = 0; c < 12; c++) {
            int idx = tid + c * 256;           // 0..3071
            int row = idx >> 3;                // 0..383
            int g   = idx & 7;                 // 16B granule in 128B row
            const char* gp;
            if (row < BM_T)
                gp = (const char*)Asrc + (size_t)(m0 + row) * (IN_F * 2) + kb + g * 16;
            else
                gp = (const char*)Bsrc + (size_t)(n0 + row - BM_T) * (IN_F * 2) + kb + g * 16;
            cp16(base + row * ROWB + g * 16, gp);
        }
        cp_commit();
    };

    float acc[4][8][4];
    #pragma unroll
    for (int i = 0; i < 4; i++)
        #pragma unroll
        for (int j = 0; j < 8; j++)
            #pragma unroll
            for (int r = 0; r < 4; r++) acc[i][j][r] = 0.f;

    issue_chunk(0);
    issue_chunk(1);

    uint32_t a[2][4][4], b[2][8][2];   // double-buffered fragments

    auto load_frags = [&](uint32_t aB, uint32_t bB, int ks, int pb) {
        const uint32_t k0b = (uint32_t)ks * 32;
        #pragma unroll
        for (int i = 0; i < 4; i++)
            ldsm4(a[pb][i][0], a[pb][i][1], a[pb][i][2], a[pb][i][3],
                  aB + (uint32_t)i * (16 * ROWB) + k0b);
        #pragma unroll
        for (int jj = 0; jj < 4; jj++)
            ldsm4(b[pb][2*jj][0], b[pb][2*jj][1], b[pb][2*jj+1][0], b[pb][2*jj+1][1],
                  bB + (uint32_t)jj * (16 * ROWB) + k0b);
    };

    for (int s = 0; s < NCHUNKG; s++) {
        if (s == NCHUNKG - 1) cp_wait<0>(); else cp_wait<1>();
        __syncthreads();
        // refill early: stage (s+2)%3 was fully consumed before the barrier above
        if (s + 2 < NCHUNKG) issue_chunk(s + 2);

        const uint32_t base = sb + (uint32_t)(s % NSTAGEG) * STAGE_B;
        const uint32_t aB = base + aoff;
        const uint32_t bB = base + BM_T * ROWB + boff;

        load_frags(aB, bB, 0, 0);
        #pragma unroll
        for (int ks = 0; ks < 4; ks++) {
            const int cur = ks & 1;
            if (ks < 3) load_frags(aB, bB, ks + 1, cur ^ 1);  // prefetch next under MMAs
            #pragma unroll
            for (int i = 0; i < 4; i++)
                #pragma unroll
                for (int j = 0; j < 8; j++)
                    mma_bf16(acc[i][j], a[cur][i], b[cur][j]);
        }
    }

    // writeback
    #pragma unroll
    for (int i = 0; i < 4; i++) {
        int r0 = m0 + wm * 64 + i * 16 + gr;
        #pragma unroll
        for (int j = 0; j < 8; j++) {
            int cc = n0 + wn * 64 + j * 8 + 2 * tig;
            *reinterpret_cast<float2*>(C + (size_t)r0 * OUT_F + cc) =
                make_float2(acc[i][j][0], acc[i][j][1]);
            *reinterpret_cast<float2*>(C + (size_t)(r0 + 8) * OUT_F + cc) =
                make_float2(acc[i][j][2], acc[i][j][3]);
        }
    }
}

// ---------------- Top-2 per batch row: one warp per row -------------------
__device__ __forceinline__ void merge_top2(float& av1, int& ai1, float& av2, int& ai2,
                                           float bv1, int bi1, float bv2, int bi2) {
    if (bv1 > av1 || (bv1 == av1 && bi1 < ai1)) {
        float nv2; int ni2;
        if (av1 > bv2 || (av1 == bv2 && ai1 < bi2)) { nv2 = av1; ni2 = ai1; }
        else                                         { nv2 = bv2; ni2 = bi2; }
        av1 = bv1; ai1 = bi1; av2 = nv2; ai2 = ni2;
    } else {
        if (bv1 > av2 || (bv1 == av2 && bi1 < ai2)) { av2 = bv1; ai2 = bi1; }
    }
}

__global__ __launch_bounds__(256)
void top2_kernel(const float* __restrict__ y) {
    const int warp = threadIdx.x >> 5;
    const int lane = threadIdx.x & 31;
    const int row  = blockIdx.x * 8 + warp;

    const float4* r4 = reinterpret_cast<const float4*>(y + (size_t)row * OUT_F);
    float v1 = -CUDART_INF_F, v2 = -CUDART_INF_F;
    int   i1 = 0x7fffffff,    i2 = 0x7fffffff;

    auto upd = [&](float v, int j) {
        if (v > v1) { v2 = v1; i2 = i1; v1 = v; i1 = j; }
        else if (v > v2) { v2 = v; i2 = j; }
    };
    #pragma unroll
    for (int k = 0; k < 16; k++) {             // 512 float4s per row / 32 lanes
        int j4 = lane + 32 * k;
        float4 v = r4[j4];
        int jb = 4 * j4;
        upd(v.x, jb); upd(v.y, jb + 1); upd(v.z, jb + 2); upd(v.w, jb + 3);
    }

    #pragma unroll
    for (int off = 16; off > 0; off >>= 1) {
        float ov1 = __shfl_xor_sync(0xffffffffu, v1, off);
        int   oi1 = __shfl_xor_sync(0xffffffffu, i1, off);
        float ov2 = __shfl_xor_sync(0xffffffffu, v2, off);
        int   oi2 = __shfl_xor_sync(0xffffffffu, i2, off);
        merge_top2(v1, i1, v2, i2, ov1, oi1, ov2, oi2);
    }
    if (lane == 0) { g_idx0[row] = i1; g_idx1[row] = i2; }
}

// ---------------- ds = yl@x - xx*W, and nc = max|ds| ----------------
// One block per output unit o. Thread t owns columns 4t..4t+3 in registers.
#define CHUNK 256
__global__ __launch_bounds__(256)
void update_kernel(const float* __restrict__ x, const float* __restrict__ w,
                   const float* __restrict__ y, int B, int OUT) {
    const int o   = blockIdx.x;
    const int tid = threadIdx.x;

    __shared__ int   mb[CHUNK];
    __shared__ float mc[CHUNK];
    __shared__ int   mcount;
    __shared__ float sxx;

    float4 acc = make_float4(0.f, 0.f, 0.f, 0.f);
    if (tid == 0) sxx = 0.f;
    __syncthreads();

    float xxloc = 0.f;
    for (int b0 = 0; b0 < B; b0 += CHUNK) {
        if (tid == 0) mcount = 0;
        __syncthreads();
        int b = b0 + tid;
        float c = 0.f;
        if (g_idx0[b] == o)      c = 1.0f;
        else if (g_idx1[b] == o) c = -ANTI;
        if (c != 0.f) {
            int slot = atomicAdd(&mcount, 1);
            mb[slot] = b;
            mc[slot] = c;
            xxloc += c * y[(size_t)b * OUT + o];
        }
        __syncthreads();
        const int n = mcount;
        for (int m = 0; m < n; m++) {
            const float4* xr4 = reinterpret_cast<const float4*>(x + (size_t)mb[m] * IN_F);
            const float cm = mc[m];
            float4 xv = xr4[tid];
            acc.x = fmaf(cm, xv.x, acc.x);
            acc.y = fmaf(cm, xv.y, acc.y);
            acc.z = fmaf(cm, xv.z, acc.z);
            acc.w = fmaf(cm, xv.w, acc.w);
        }
        __syncthreads();
    }
    if (xxloc != 0.f) atomicAdd(&sxx, xxloc);
    __syncthreads();

    const float xx = sxx;
    const float4* w4 = reinterpret_cast<const float4*>(w + (size_t)o * IN_F);
    float4 wv = w4[tid];
    float4 d;
    d.x = acc.x - xx * wv.x;
    d.y = acc.y - xx * wv.y;
    d.z = acc.z - xx * wv.z;
    d.w = acc.w - xx * wv.w;
    reinterpret_cast<float4*>(g_ds + (size_t)o * IN_F)[tid] = d;

    float lmax = fmaxf(fmaxf(fabsf(d.x), fabsf(d.y)), fmaxf(fabsf(d.z), fabsf(d.w)));
    #pragma unroll
    for (int off = 16; off > 0; off >>= 1)
        lmax = fmaxf(lmax, __shfl_xor_sync(0xffffffffu, lmax, off));
    __shared__ float smax[8];
    if ((tid & 31) == 0) smax[tid >> 5] = lmax;
    __syncthreads();
    if (tid == 0) {
        float m = smax[0];
        #pragma unroll
        for (int k = 1; k < 8; k++) m = fmaxf(m, smax[k]);
        atomicMax(&g_nc, __float_as_uint(m));
    }
}

// ---------------- new_w = w + LR * ds / nc ----------------
__global__ __launch_bounds__(256)
void finalize_kernel(const float4* __restrict__ w4, float4* __restrict__ neww4, int n4) {
    const float inv = LR / __uint_as_float(g_nc);
    int i = blockIdx.x * blockDim.x + threadIdx.x;
    if (i < n4) {
        const float4* ds4 = reinterpret_cast<const float4*>(g_ds);
        float4 d = ds4[i];
        float4 v = w4[i];
        v.x = fmaf(d.x, inv, v.x);
        v.y = fmaf(d.y, inv, v.y);
        v.z = fmaf(d.z, inv, v.z);
        v.w = fmaf(d.w, inv, v.w);
        neww4[i] = v;
    }
}

// ---------------- launch ----------------
extern "C" void kernel_launch(void* const* d_in, const int* in_sizes, int n_in,
                              void* d_out, int out_size) {
    const float* x = (const float*)d_in[0];
    const float* w = (const float*)d_in[1];
    if (n_in >= 2 && in_sizes[0] == OUT_F * IN_F && in_sizes[1] == BATCH * IN_F) {
        w = (const float*)d_in[0];
        x = (const float*)d_in[1];
    }

    float* y_out = (float*)d_out;                       // [BATCH, OUT_F]
    float* w_out = y_out + (size_t)BATCH * OUT_F;       // [OUT_F, IN_F]

    __nv_bfloat16 *xhi, *xlo, *whi, *wlo;
    cudaGetSymbolAddress((void**)&xhi, g_xhi);
    cudaGetSymbolAddress((void**)&xlo, g_xlo);
    cudaGetSymbolAddress((void**)&whi, g_whi);
    cudaGetSymbolAddress((void**)&wlo, g_wlo);

    // 0) fused bf16 splits (+ nc reset)
    {
        int n4x = BATCH * IN_F / 4;
        int n4t = n4x + OUT_F * IN_F / 4;
        split_bf16_fused<<<(n4t + 255) / 256, 256>>>(
            (const float4*)x, (const float4*)w,
            (uint2*)xhi, (uint2*)xlo, (uint2*)whi, (uint2*)wlo, n4x, n4t);
    }
    // 1) y = x @ W^T via bf16 mma.sync, 3-product split folded into K
    {
        cudaFuncSetAttribute(gemm_bf16_kernel,
                             cudaFuncAttributeMaxDynamicSharedMemorySize, SMEM_GEMM);
        dim3 grid(OUT_F / BN_T, BATCH / BM_T);
        gemm_bf16_kernel<<<grid, 256, SMEM_GEMM>>>(xhi, xlo, whi, wlo, y_out);
    }
    // 2) top-2 per batch row (warp per row)
    top2_kernel<<<BATCH / 8, 256>>>(y_out);
    // 3) ds + global max
    update_kernel<<<OUT_F, 256>>>(x, w, y_out, BATCH, OUT_F);
    // 4) finalize
    {
        int n4 = OUT_F * IN_F / 4;
        finalize_kernel<<<(n4 + 255) / 256, 256>>>((const float4*)w, (float4*)w_out, n4);
    }
}

// round 10
// speedup vs baseline: 2.3047x; 1.0605x over previous
#include <cuda_runtime.h>
#include <cuda_bf16.h>
#include <math_constants.h>
#include <cstdint>

// Problem constants
#define IN_F   1024
#define OUT_F  2048
#define BATCH  8192
#define LR     0.02f
#define ANTI   0.4f
#define PREC   1e-30f

// ---------------- scratch (no allocations allowed) ----------------
__device__ float          g_ds[(size_t)OUT_F * IN_F];
__device__ int            g_idx0[BATCH];
__device__ int            g_idx1[BATCH];
__device__ unsigned int   g_nc;
__device__ int            g_cnt[OUT_F];        // counts, then segment cursors
__device__ int            g_rowptr[OUT_F + 1];
__device__ int            g_blist[2 * BATCH];
__device__ float          g_clist[2 * BATCH];
// bf16 split matrices
__device__ __nv_bfloat16  g_xhi[(size_t)BATCH * IN_F];
__device__ __nv_bfloat16  g_xlo[(size_t)BATCH * IN_F];
__device__ __nv_bfloat16  g_whi[(size_t)OUT_F * IN_F];
__device__ __nv_bfloat16  g_wlo[(size_t)OUT_F * IN_F];

// ================= helpers =================
__device__ __forceinline__ uint32_t smem_u32(const void* p) {
    uint32_t a;
    asm("{ .reg .u64 t; cvta.to.shared.u64 t, %1; cvt.u32.u64 %0, t; }" : "=r"(a) : "l"(p));
    return a;
}
__device__ __forceinline__ void cp16(uint32_t sm, const void* g) {
    asm volatile("cp.async.cg.shared.global [%0], [%1], 16;" :: "r"(sm), "l"(g) : "memory");
}
__device__ __forceinline__ void cp_commit() {
    asm volatile("cp.async.commit_group;" ::: "memory");
}
template <int N>
__device__ __forceinline__ void cp_wait() {
    asm volatile("cp.async.wait_group %0;" :: "n"(N) : "memory");
}
__device__ __forceinline__ void mma_bf16(float* d, const uint32_t* a, const uint32_t* b) {
    asm volatile(
        "mma.sync.aligned.m16n8k16.row.col.f32.bf16.bf16.f32 "
        "{%0,%1,%2,%3}, {%4,%5,%6,%7}, {%8,%9}, {%0,%1,%2,%3};"
        : "+f"(d[0]), "+f"(d[1]), "+f"(d[2]), "+f"(d[3])
        : "r"(a[0]), "r"(a[1]), "r"(a[2]), "r"(a[3]), "r"(b[0]), "r"(b[1]));
}
__device__ __forceinline__ void ldsm4(uint32_t& r0, uint32_t& r1, uint32_t& r2, uint32_t& r3,
                                      uint32_t addr) {
    asm volatile("ldmatrix.sync.aligned.m8n8.x4.shared.b16 {%0,%1,%2,%3}, [%4];"
                 : "=r"(r0), "=r"(r1), "=r"(r2), "=r"(r3) : "r"(addr));
}

// ================= fused split kernel: {x,w} -> (bf16 hi, bf16 lo) =========
__global__ __launch_bounds__(256)
void split_bf16_fused(const float4* __restrict__ x4, const float4* __restrict__ w4,
                      uint2* __restrict__ xhi, uint2* __restrict__ xlo,
                      uint2* __restrict__ whi, uint2* __restrict__ wlo,
                      int n4x, int n4tot) {
    int i = blockIdx.x * blockDim.x + threadIdx.x;
    if (i == 0) g_nc = __float_as_uint(PREC);   // reset for this launch
    if (i < OUT_F) g_cnt[i] = 0;                // zero match counters
    if (i >= n4tot) return;
    const float4* src; uint2 *hi, *lo; int idx;
    if (i < n4x) { src = x4; hi = xhi; lo = xlo; idx = i; }
    else         { src = w4; hi = whi; lo = wlo; idx = i - n4x; }
    float4 v = src[idx];
    __nv_bfloat16 h0 = __float2bfloat16(v.x);
    __nv_bfloat16 h1 = __float2bfloat16(v.y);
    __nv_bfloat16 h2 = __float2bfloat16(v.z);
    __nv_bfloat16 h3 = __float2bfloat16(v.w);
    __nv_bfloat16 l0 = __float2bfloat16(v.x - __bfloat162float(h0));
    __nv_bfloat16 l1 = __float2bfloat16(v.y - __bfloat162float(h1));
    __nv_bfloat16 l2 = __float2bfloat16(v.z - __bfloat162float(h2));
    __nv_bfloat16 l3 = __float2bfloat16(v.w - __bfloat162float(h3));
    __nv_bfloat162 hp0 = __halves2bfloat162(h0, h1);
    __nv_bfloat162 hp1 = __halves2bfloat162(h2, h3);
    __nv_bfloat162 lp0 = __halves2bfloat162(l0, l1);
    __nv_bfloat162 lp1 = __halves2bfloat162(l2, l3);
    uint2 hv, lv;
    hv.x = *reinterpret_cast<uint32_t*>(&hp0); hv.y = *reinterpret_cast<uint32_t*>(&hp1);
    lv.x = *reinterpret_cast<uint32_t*>(&lp0); lv.y = *reinterpret_cast<uint32_t*>(&lp1);
    hi[idx] = hv; lo[idx] = lv;
}

// ================= bf16 mma.sync GEMM (3-product split folded into K) =====
#define BM_T 128
#define BN_T 256
#define ROWB 144u
#define STAGE_B ((BM_T + BN_T) * ROWB)
#define NSTAGEG 3
#define NCHUNKG 48
#define SMEM_GEMM (NSTAGEG * STAGE_B)

__global__ __launch_bounds__(256, 1)
void gemm_bf16_kernel(const __nv_bfloat16* __restrict__ Xhi,
                      const __nv_bfloat16* __restrict__ Xlo,
                      const __nv_bfloat16* __restrict__ Whi,
                      const __nv_bfloat16* __restrict__ Wlo,
                      float* __restrict__ C) {
    extern __shared__ char smem[];
    const uint32_t sb = smem_u32(smem);
    const int tid  = threadIdx.x;
    const int wid  = tid >> 5;
    const int lane = tid & 31;
    const int gr   = lane >> 2;
    const int tig  = lane & 3;
    const int wm   = wid & 1;
    const int wn   = wid >> 1;
    const int m0 = blockIdx.y * BM_T;
    const int n0 = blockIdx.x * BN_T;

    const uint32_t aoff = (uint32_t)(wm * 64 + (lane & 15)) * ROWB + (uint32_t)(lane >> 4) * 16;
    const uint32_t boff = (uint32_t)(wn * 64 + ((lane >> 4) * 8) + (lane & 7)) * ROWB
                        + (uint32_t)((lane >> 3) & 1) * 16;

    auto issue_chunk = [&](int s) {
        const int region = s >> 4;
        const int kb = (s & 15) * 128;
        const __nv_bfloat16* Asrc = (region == 1) ? Xlo : Xhi;
        const __nv_bfloat16* Bsrc = (region == 2) ? Wlo : Whi;
        const uint32_t base = sb + (uint32_t)(s % NSTAGEG) * STAGE_B;
        #pragma unroll
        for (int c = 0; c < 12; c++) {
            int idx = tid + c * 256;
            int row = idx >> 3, g = idx & 7;
            const char* gp;
            if (row < BM_T)
                gp = (const char*)Asrc + (size_t)(m0 + row) * (IN_F * 2) + kb + g * 16;
            else
                gp = (const char*)Bsrc + (size_t)(n0 + row - BM_T) * (IN_F * 2) + kb + g * 16;
            cp16(base + row * ROWB + g * 16, gp);
        }
        cp_commit();
    };

    float acc[4][8][4];
    #pragma unroll
    for (int i = 0; i < 4; i++)
        #pragma unroll
        for (int j = 0; j < 8; j++)
            #pragma unroll
            for (int r = 0; r < 4; r++) acc[i][j][r] = 0.f;

    issue_chunk(0);
    issue_chunk(1);

    uint32_t a[2][4][4], b[2][8][2];
    auto load_frags = [&](uint32_t aB, uint32_t bB, int ks, int pb) {
        const uint32_t k0b = (uint32_t)ks * 32;
        #pragma unroll
        for (int i = 0; i < 4; i++)
            ldsm4(a[pb][i][0], a[pb][i][1], a[pb][i][2], a[pb][i][3],
                  aB + (uint32_t)i * (16 * ROWB) + k0b);
        #pragma unroll
        for (int jj = 0; jj < 4; jj++)
            ldsm4(b[pb][2*jj][0], b[pb][2*jj][1], b[pb][2*jj+1][0], b[pb][2*jj+1][1],
                  bB + (uint32_t)jj * (16 * ROWB) + k0b);
    };

    for (int s = 0; s < NCHUNKG; s++) {
        if (s == NCHUNKG - 1) cp_wait<0>(); else cp_wait<1>();
        __syncthreads();
        if (s + 2 < NCHUNKG) issue_chunk(s + 2);

        const uint32_t base = sb + (uint32_t)(s % NSTAGEG) * STAGE_B;
        const uint32_t aB = base + aoff;
        const uint32_t bB = base + BM_T * ROWB + boff;

        load_frags(aB, bB, 0, 0);
        #pragma unroll
        for (int ks = 0; ks < 4; ks++) {
            const int cur = ks & 1;
            if (ks < 3) load_frags(aB, bB, ks + 1, cur ^ 1);
            #pragma unroll
            for (int i = 0; i < 4; i++)
                #pragma unroll
                for (int j = 0; j < 8; j++)
                    mma_bf16(acc[i][j], a[cur][i], b[cur][j]);
        }
    }

    #pragma unroll
    for (int i = 0; i < 4; i++) {
        int r0 = m0 + wm * 64 + i * 16 + gr;
        #pragma unroll
        for (int j = 0; j < 8; j++) {
            int cc = n0 + wn * 64 + j * 8 + 2 * tig;
            *reinterpret_cast<float2*>(C + (size_t)r0 * OUT_F + cc) =
                make_float2(acc[i][j][0], acc[i][j][1]);
            *reinterpret_cast<float2*>(C + (size_t)(r0 + 8) * OUT_F + cc) =
                make_float2(acc[i][j][2], acc[i][j][3]);
        }
    }
}

// ---------------- Top-2 per batch row (warp per row) + match counting -----
__device__ __forceinline__ void merge_top2(float& av1, int& ai1, float& av2, int& ai2,
                                           float bv1, int bi1, float bv2, int bi2) {
    if (bv1 > av1 || (bv1 == av1 && bi1 < ai1)) {
        float nv2; int ni2;
        if (av1 > bv2 || (av1 == bv2 && ai1 < bi2)) { nv2 = av1; ni2 = ai1; }
        else                                         { nv2 = bv2; ni2 = bi2; }
        av1 = bv1; ai1 = bi1; av2 = nv2; ai2 = ni2;
    } else {
        if (bv1 > av2 || (bv1 == av2 && bi1 < ai2)) { av2 = bv1; ai2 = bi1; }
    }
}

__global__ __launch_bounds__(256)
void top2_kernel(const float* __restrict__ y) {
    const int warp = threadIdx.x >> 5;
    const int lane = threadIdx.x & 31;
    const int row  = blockIdx.x * 8 + warp;

    const float4* r4 = reinterpret_cast<const float4*>(y + (size_t)row * OUT_F);
    float v1 = -CUDART_INF_F, v2 = -CUDART_INF_F;
    int   i1 = 0x7fffffff,    i2 = 0x7fffffff;

    auto upd = [&](float v, int j) {
        if (v > v1) { v2 = v1; i2 = i1; v1 = v; i1 = j; }
        else if (v > v2) { v2 = v; i2 = j; }
    };
    #pragma unroll
    for (int k = 0; k < 16; k++) {
        int j4 = lane + 32 * k;
        float4 v = r4[j4];
        int jb = 4 * j4;
        upd(v.x, jb); upd(v.y, jb + 1); upd(v.z, jb + 2); upd(v.w, jb + 3);
    }

    #pragma unroll
    for (int off = 16; off > 0; off >>= 1) {
        float ov1 = __shfl_xor_sync(0xffffffffu, v1, off);
        int   oi1 = __shfl_xor_sync(0xffffffffu, i1, off);
        float ov2 = __shfl_xor_sync(0xffffffffu, v2, off);
        int   oi2 = __shfl_xor_sync(0xffffffffu, i2, off);
        merge_top2(v1, i1, v2, i2, ov1, oi1, ov2, oi2);
    }
    if (lane == 0) {
        g_idx0[row] = i1; g_idx1[row] = i2;
        atomicAdd(&g_cnt[i1], 1);
        atomicAdd(&g_cnt[i2], 1);
    }
}

// ---------------- exclusive scan of g_cnt -> g_rowptr; reseed g_cnt -------
__global__ __launch_bounds__(1024)
void scan_kernel() {
    __shared__ int bufA[OUT_F], bufB[OUT_F];
    const int tid = threadIdx.x;
    bufA[tid] = g_cnt[tid];
    bufA[tid + 1024] = g_cnt[tid + 1024];
    __syncthreads();
    int *in = bufA, *out = bufB;
    for (int off = 1; off < OUT_F; off <<= 1) {
        #pragma unroll
        for (int r = 0; r < 2; r++) {
            int i = tid + r * 1024;
            out[i] = in[i] + ((i >= off) ? in[i - off] : 0);
        }
        __syncthreads();
        int* t = in; in = out; out = t;
    }
    // 'in' holds inclusive scan
    #pragma unroll
    for (int r = 0; r < 2; r++) {
        int i = tid + r * 1024;
        int excl = (i == 0) ? 0 : in[i - 1];
        g_rowptr[i] = excl;
        g_cnt[i]    = excl;       // segment cursor for fill
        if (i == OUT_F - 1) g_rowptr[OUT_F] = in[i];
    }
}

// ---------------- fill CSR lists ------------------------------------------
__global__ __launch_bounds__(256)
void fill_kernel() {
    int b = blockIdx.x * blockDim.x + threadIdx.x;
    if (b >= BATCH) return;
    int o0 = g_idx0[b];
    int p0 = atomicAdd(&g_cnt[o0], 1);
    g_blist[p0] = b; g_clist[p0] = 1.0f;
    int o1 = g_idx1[b];
    int p1 = atomicAdd(&g_cnt[o1], 1);
    g_blist[p1] = b; g_clist[p1] = -ANTI;
}

// ---------------- ds = yl@x - xx*W, and nc = max|ds| (CSR) ----------------
__global__ __launch_bounds__(256)
void update_kernel(const float* __restrict__ x, const float* __restrict__ w,
                   const float* __restrict__ y, int OUT) {
    const int o   = blockIdx.x;
    const int tid = threadIdx.x;
    const int start = g_rowptr[o];
    const int end   = g_rowptr[o + 1];

    __shared__ float sxx;
    if (tid == 0) sxx = 0.f;
    __syncthreads();

    // xx[o] = sum c * y[b, o]
    float xxloc = 0.f;
    for (int m = start + tid; m < end; m += 256)
        xxloc += g_clist[m] * y[(size_t)g_blist[m] * OUT_F + o];
    #pragma unroll
    for (int off = 16; off > 0; off >>= 1)
        xxloc += __shfl_xor_sync(0xffffffffu, xxloc, off);
    if ((tid & 31) == 0 && xxloc != 0.f) atomicAdd(&sxx, xxloc);
    __syncthreads();
    const float xx = sxx;

    // accumulate matched x rows; thread t owns cols 4t..4t+3
    float4 acc = make_float4(0.f, 0.f, 0.f, 0.f);
    for (int m = start; m < end; m++) {
        const float c = g_clist[m];
        const float4 xv = reinterpret_cast<const float4*>(
            x + (size_t)g_blist[m] * IN_F)[tid];
        acc.x = fmaf(c, xv.x, acc.x);
        acc.y = fmaf(c, xv.y, acc.y);
        acc.z = fmaf(c, xv.z, acc.z);
        acc.w = fmaf(c, xv.w, acc.w);
    }

    const float4 wv = reinterpret_cast<const float4*>(w + (size_t)o * IN_F)[tid];
    float4 d;
    d.x = acc.x - xx * wv.x;
    d.y = acc.y - xx * wv.y;
    d.z = acc.z - xx * wv.z;
    d.w = acc.w - xx * wv.w;
    reinterpret_cast<float4*>(g_ds + (size_t)o * IN_F)[tid] = d;

    float lmax = fmaxf(fmaxf(fabsf(d.x), fabsf(d.y)), fmaxf(fabsf(d.z), fabsf(d.w)));
    #pragma unroll
    for (int off = 16; off > 0; off >>= 1)
        lmax = fmaxf(lmax, __shfl_xor_sync(0xffffffffu, lmax, off));
    __shared__ float smax[8];
    if ((tid & 31) == 0) smax[tid >> 5] = lmax;
    __syncthreads();
    if (tid == 0) {
        float m = smax[0];
        #pragma unroll
        for (int k = 1; k < 8; k++) m = fmaxf(m, smax[k]);
        atomicMax(&g_nc, __float_as_uint(m));
    }
}

// ---------------- new_w = w + LR * ds / nc ----------------
__global__ __launch_bounds__(256)
void finalize_kernel(const float4* __restrict__ w4, float4* __restrict__ neww4, int n4) {
    const float inv = LR / __uint_as_float(g_nc);
    int i = blockIdx.x * blockDim.x + threadIdx.x;
    if (i < n4) {
        const float4* ds4 = reinterpret_cast<const float4*>(g_ds);
        float4 d = ds4[i];
        float4 v = w4[i];
        v.x = fmaf(d.x, inv, v.x);
        v.y = fmaf(d.y, inv, v.y);
        v.z = fmaf(d.z, inv, v.z);
        v.w = fmaf(d.w, inv, v.w);
        neww4[i] = v;
    }
}

// ---------------- launch ----------------
extern "C" void kernel_launch(void* const* d_in, const int* in_sizes, int n_in,
                              void* d_out, int out_size) {
    const float* x = (const float*)d_in[0];
    const float* w = (const float*)d_in[1];
    if (n_in >= 2 && in_sizes[0] == OUT_F * IN_F && in_sizes[1] == BATCH * IN_F) {
        w = (const float*)d_in[0];
        x = (const float*)d_in[1];
    }

    float* y_out = (float*)d_out;                       // [BATCH, OUT_F]
    float* w_out = y_out + (size_t)BATCH * OUT_F;       // [OUT_F, IN_F]

    __nv_bfloat16 *xhi, *xlo, *whi, *wlo;
    cudaGetSymbolAddress((void**)&xhi, g_xhi);
    cudaGetSymbolAddress((void**)&xlo, g_xlo);
    cudaGetSymbolAddress((void**)&whi, g_whi);
    cudaGetSymbolAddress((void**)&wlo, g_wlo);

    // 0) fused bf16 splits (+ nc/counter reset)
    {
        int n4x = BATCH * IN_F / 4;
        int n4t = n4x + OUT_F * IN_F / 4;
        split_bf16_fused<<<(n4t + 255) / 256, 256>>>(
            (const float4*)x, (const float4*)w,
            (uint2*)xhi, (uint2*)xlo, (uint2*)whi, (uint2*)wlo, n4x, n4t);
    }
    // 1) y = x @ W^T via bf16 mma.sync
    {
        cudaFuncSetAttribute(gemm_bf16_kernel,
                             cudaFuncAttributeMaxDynamicSharedMemorySize, SMEM_GEMM);
        dim3 grid(OUT_F / BN_T, BATCH / BM_T);
        gemm_bf16_kernel<<<grid, 256, SMEM_GEMM>>>(xhi, xlo, whi, wlo, y_out);
    }
    // 2) top-2 per batch row + match counting
    top2_kernel<<<BATCH / 8, 256>>>(y_out);
    // 3) CSR build: scan + fill
    scan_kernel<<<1, 1024>>>();
    fill_kernel<<<BATCH / 256, 256>>>();
    // 4) ds + global max (CSR-driven)
    update_kernel<<<OUT_F, 256>>>(x, w, y_out, OUT_F);
    // 5) finalize
    {
        int n4 = OUT_F * IN_F / 4;
        finalize_kernel<<<(n4 + 255) / 256, 256>>>((const float4*)w, (float4*)w_out, n4);
    }
}

// round 11
// speedup vs baseline: 2.6403x; 1.1456x over previous
#include <cuda_runtime.h>
#include <cuda_bf16.h>
#include <math_constants.h>
#include <cstdint>

// Problem constants
#define IN_F   1024
#define OUT_F  2048
#define BATCH  8192
#define LR     0.02f
#define ANTI   0.4f
#define PREC   1e-30f

// ---------------- scratch (no allocations allowed) ----------------
__device__ float          g_ds[(size_t)OUT_F * IN_F];
__device__ int            g_idx0[BATCH];
__device__ int            g_idx1[BATCH];
__device__ unsigned int   g_nc;
__device__ int            g_cnt[OUT_F];        // counts, then segment cursors
__device__ int            g_rowptr[OUT_F + 1];
__device__ int            g_blist[2 * BATCH];
__device__ float          g_clist[2 * BATCH];
// bf16 split matrices
__device__ __nv_bfloat16  g_xhi[(size_t)BATCH * IN_F];
__device__ __nv_bfloat16  g_xlo[(size_t)BATCH * IN_F];
__device__ __nv_bfloat16  g_whi[(size_t)OUT_F * IN_F];
__device__ __nv_bfloat16  g_wlo[(size_t)OUT_F * IN_F];

// ================= helpers =================
__device__ __forceinline__ uint32_t smem_u32(const void* p) {
    uint32_t a;
    asm("{ .reg .u64 t; cvta.to.shared.u64 t, %1; cvt.u32.u64 %0, t; }" : "=r"(a) : "l"(p));
    return a;
}
__device__ __forceinline__ void cp16(uint32_t sm, const void* g) {
    asm volatile("cp.async.cg.shared.global [%0], [%1], 16;" :: "r"(sm), "l"(g) : "memory");
}
__device__ __forceinline__ void cp_commit() {
    asm volatile("cp.async.commit_group;" ::: "memory");
}
template <int N>
__device__ __forceinline__ void cp_wait() {
    asm volatile("cp.async.wait_group %0;" :: "n"(N) : "memory");
}
__device__ __forceinline__ void mma_bf16(float* d, const uint32_t* a, const uint32_t* b) {
    asm volatile(
        "mma.sync.aligned.m16n8k16.row.col.f32.bf16.bf16.f32 "
        "{%0,%1,%2,%3}, {%4,%5,%6,%7}, {%8,%9}, {%0,%1,%2,%3};"
        : "+f"(d[0]), "+f"(d[1]), "+f"(d[2]), "+f"(d[3])
        : "r"(a[0]), "r"(a[1]), "r"(a[2]), "r"(a[3]), "r"(b[0]), "r"(b[1]));
}
__device__ __forceinline__ void ldsm4(uint32_t& r0, uint32_t& r1, uint32_t& r2, uint32_t& r3,
                                      uint32_t addr) {
    asm volatile("ldmatrix.sync.aligned.m8n8.x4.shared.b16 {%0,%1,%2,%3}, [%4];"
                 : "=r"(r0), "=r"(r1), "=r"(r2), "=r"(r3) : "r"(addr));
}

// ================= fused split kernel: {x,w} -> (bf16 hi, bf16 lo) =========
__global__ __launch_bounds__(256)
void split_bf16_fused(const float4* __restrict__ x4, const float4* __restrict__ w4,
                      uint2* __restrict__ xhi, uint2* __restrict__ xlo,
                      uint2* __restrict__ whi, uint2* __restrict__ wlo,
                      int n4x, int n4tot) {
    int i = blockIdx.x * blockDim.x + threadIdx.x;
    if (i == 0) g_nc = __float_as_uint(PREC);   // reset for this launch
    if (i < OUT_F) g_cnt[i] = 0;                // zero match counters
    if (i >= n4tot) return;
    const float4* src; uint2 *hi, *lo; int idx;
    if (i < n4x) { src = x4; hi = xhi; lo = xlo; idx = i; }
    else         { src = w4; hi = whi; lo = wlo; idx = i - n4x; }
    float4 v = src[idx];
    __nv_bfloat16 h0 = __float2bfloat16(v.x);
    __nv_bfloat16 h1 = __float2bfloat16(v.y);
    __nv_bfloat16 h2 = __float2bfloat16(v.z);
    __nv_bfloat16 h3 = __float2bfloat16(v.w);
    __nv_bfloat16 l0 = __float2bfloat16(v.x - __bfloat162float(h0));
    __nv_bfloat16 l1 = __float2bfloat16(v.y - __bfloat162float(h1));
    __nv_bfloat16 l2 = __float2bfloat16(v.z - __bfloat162float(h2));
    __nv_bfloat16 l3 = __float2bfloat16(v.w - __bfloat162float(h3));
    __nv_bfloat162 hp0 = __halves2bfloat162(h0, h1);
    __nv_bfloat162 hp1 = __halves2bfloat162(h2, h3);
    __nv_bfloat162 lp0 = __halves2bfloat162(l0, l1);
    __nv_bfloat162 lp1 = __halves2bfloat162(l2, l3);
    uint2 hv, lv;
    hv.x = *reinterpret_cast<uint32_t*>(&hp0); hv.y = *reinterpret_cast<uint32_t*>(&hp1);
    lv.x = *reinterpret_cast<uint32_t*>(&lp0); lv.y = *reinterpret_cast<uint32_t*>(&lp1);
    hi[idx] = hv; lo[idx] = lv;
}

// ================= bf16 mma.sync GEMM (3-product split folded into K) =====
// 128x128 CTA tiles, 2 CTAs/SM, 2-stage cp.async pipeline.
#define BM_T 128
#define BN_T 128
#define ROWB 144u
#define STAGE_B ((BM_T + BN_T) * ROWB)   // 256*144 = 36864
#define NSTAGEG 2
#define NCHUNKG 48
#define SMEM_GEMM (NSTAGEG * STAGE_B)    // 73728

__global__ __launch_bounds__(256, 2)
void gemm_bf16_kernel(const __nv_bfloat16* __restrict__ Xhi,
                      const __nv_bfloat16* __restrict__ Xlo,
                      const __nv_bfloat16* __restrict__ Whi,
                      const __nv_bfloat16* __restrict__ Wlo,
                      float* __restrict__ C) {
    extern __shared__ char smem[];
    const uint32_t sb = smem_u32(smem);
    const int tid  = threadIdx.x;
    const int wid  = tid >> 5;
    const int lane = tid & 31;
    const int gr   = lane >> 2;
    const int tig  = lane & 3;
    const int wm   = wid & 1;      // 2 warp rows (64 each)
    const int wn   = wid >> 1;     // 4 warp cols (32 each)
    const int m0 = blockIdx.y * BM_T;
    const int n0 = blockIdx.x * BN_T;

    const uint32_t aoff = (uint32_t)(wm * 64 + (lane & 15)) * ROWB + (uint32_t)(lane >> 4) * 16;
    const uint32_t boff = (uint32_t)(wn * 32 + ((lane >> 4) * 8) + (lane & 7)) * ROWB
                        + (uint32_t)((lane >> 3) & 1) * 16;

    auto issue_chunk = [&](int s) {
        const int region = s >> 4;
        const int kb = (s & 15) * 128;
        const __nv_bfloat16* Asrc = (region == 1) ? Xlo : Xhi;
        const __nv_bfloat16* Bsrc = (region == 2) ? Wlo : Whi;
        const uint32_t base = sb + (uint32_t)(s & 1) * STAGE_B;
        #pragma unroll
        for (int c = 0; c < 8; c++) {
            int idx = tid + c * 256;           // 0..2047
            int row = idx >> 3, g = idx & 7;   // row 0..255
            const char* gp;
            if (row < BM_T)
                gp = (const char*)Asrc + (size_t)(m0 + row) * (IN_F * 2) + kb + g * 16;
            else
                gp = (const char*)Bsrc + (size_t)(n0 + row - BM_T) * (IN_F * 2) + kb + g * 16;
            cp16(base + row * ROWB + g * 16, gp);
        }
        cp_commit();
    };

    float acc[4][4][4];
    #pragma unroll
    for (int i = 0; i < 4; i++)
        #pragma unroll
        for (int j = 0; j < 4; j++)
            #pragma unroll
            for (int r = 0; r < 4; r++) acc[i][j][r] = 0.f;

    issue_chunk(0);
    issue_chunk(1);

    for (int s = 0; s < NCHUNKG; s++) {
        if (s == NCHUNKG - 1) cp_wait<0>(); else cp_wait<1>();
        __syncthreads();

        const uint32_t base = sb + (uint32_t)(s & 1) * STAGE_B;
        const uint32_t aB = base + aoff;
        const uint32_t bB = base + BM_T * ROWB + boff;

        #pragma unroll
        for (int ks = 0; ks < 4; ks++) {
            const uint32_t k0b = (uint32_t)ks * 32;
            uint32_t a[4][4], b[4][2];
            #pragma unroll
            for (int i = 0; i < 4; i++)
                ldsm4(a[i][0], a[i][1], a[i][2], a[i][3],
                      aB + (uint32_t)i * (16 * ROWB) + k0b);
            ldsm4(b[0][0], b[0][1], b[1][0], b[1][1], bB + k0b);
            ldsm4(b[2][0], b[2][1], b[3][0], b[3][1], bB + 16 * ROWB + k0b);
            #pragma unroll
            for (int i = 0; i < 4; i++)
                #pragma unroll
                for (int j = 0; j < 4; j++)
                    mma_bf16(acc[i][j], a[i], b[j]);
        }
        __syncthreads();                       // all warps done reading stage s&1
        if (s + 2 < NCHUNKG) issue_chunk(s + 2);
    }

    #pragma unroll
    for (int i = 0; i < 4; i++) {
        int r0 = m0 + wm * 64 + i * 16 + gr;
        #pragma unroll
        for (int j = 0; j < 4; j++) {
            int cc = n0 + wn * 32 + j * 8 + 2 * tig;
            *reinterpret_cast<float2*>(C + (size_t)r0 * OUT_F + cc) =
                make_float2(acc[i][j][0], acc[i][j][1]);
            *reinterpret_cast<float2*>(C + (size_t)(r0 + 8) * OUT_F + cc) =
                make_float2(acc[i][j][2], acc[i][j][3]);
        }
    }
}

// ---------------- Top-2 per batch row (warp per row) + match counting -----
__device__ __forceinline__ void merge_top2(float& av1, int& ai1, float& av2, int& ai2,
                                           float bv1, int bi1, float bv2, int bi2) {
    if (bv1 > av1 || (bv1 == av1 && bi1 < ai1)) {
        float nv2; int ni2;
        if (av1 > bv2 || (av1 == bv2 && ai1 < bi2)) { nv2 = av1; ni2 = ai1; }
        else                                         { nv2 = bv2; ni2 = bi2; }
        av1 = bv1; ai1 = bi1; av2 = nv2; ai2 = ni2;
    } else {
        if (bv1 > av2 || (bv1 == av2 && bi1 < ai2)) { av2 = bv1; ai2 = bi1; }
    }
}

__global__ __launch_bounds__(256)
void top2_kernel(const float* __restrict__ y) {
    const int warp = threadIdx.x >> 5;
    const int lane = threadIdx.x & 31;
    const int row  = blockIdx.x * 8 + warp;

    const float4* r4 = reinterpret_cast<const float4*>(y + (size_t)row * OUT_F);
    float v1 = -CUDART_INF_F, v2 = -CUDART_INF_F;
    int   i1 = 0x7fffffff,    i2 = 0x7fffffff;

    auto upd = [&](float v, int j) {
        if (v > v1) { v2 = v1; i2 = i1; v1 = v; i1 = j; }
        else if (v > v2) { v2 = v; i2 = j; }
    };
    #pragma unroll
    for (int k = 0; k < 16; k++) {
        int j4 = lane + 32 * k;
        float4 v = r4[j4];
        int jb = 4 * j4;
        upd(v.x, jb); upd(v.y, jb + 1); upd(v.z, jb + 2); upd(v.w, jb + 3);
    }

    #pragma unroll
    for (int off = 16; off > 0; off >>= 1) {
        float ov1 = __shfl_xor_sync(0xffffffffu, v1, off);
        int   oi1 = __shfl_xor_sync(0xffffffffu, i1, off);
        float ov2 = __shfl_xor_sync(0xffffffffu, v2, off);
        int   oi2 = __shfl_xor_sync(0xffffffffu, i2, off);
        merge_top2(v1, i1, v2, i2, ov1, oi1, ov2, oi2);
    }
    if (lane == 0) {
        g_idx0[row] = i1; g_idx1[row] = i2;
        atomicAdd(&g_cnt[i1], 1);
        atomicAdd(&g_cnt[i2], 1);
    }
}

// ---------------- exclusive scan of g_cnt -> g_rowptr (shfl-based) --------
__global__ __launch_bounds__(1024)
void scan_kernel() {
    const int t = threadIdx.x;              // 0..1023, pair (2t, 2t+1)
    int v0 = g_cnt[2 * t], v1 = g_cnt[2 * t + 1];
    int s = v0 + v1;
    int incl = s;
    #pragma unroll
    for (int off = 1; off < 32; off <<= 1) {
        int n = __shfl_up_sync(0xffffffffu, incl, off);
        if ((t & 31) >= off) incl += n;
    }
    __shared__ int wsum[32];
    if ((t & 31) == 31) wsum[t >> 5] = incl;
    __syncthreads();
    if (t < 32) {
        int w = wsum[t];
        int wincl = w;
        #pragma unroll
        for (int off = 1; off < 32; off <<= 1) {
            int n = __shfl_up_sync(0xffffffffu, wincl, off);
            if (t >= off) wincl += n;
        }
        wsum[t] = wincl - w;                // exclusive warp base
    }
    __syncthreads();
    int base = wsum[t >> 5] + (incl - s);   // exclusive prefix of this pair
    g_rowptr[2 * t]     = base;
    g_rowptr[2 * t + 1] = base + v0;
    g_cnt[2 * t]        = base;             // segment cursors for fill
    g_cnt[2 * t + 1]    = base + v0;
    if (t == 1023) g_rowptr[OUT_F] = base + s;
}

// ---------------- fill CSR lists ------------------------------------------
__global__ __launch_bounds__(256)
void fill_kernel() {
    int b = blockIdx.x * blockDim.x + threadIdx.x;
    if (b >= BATCH) return;
    int o0 = g_idx0[b];
    int p0 = atomicAdd(&g_cnt[o0], 1);
    g_blist[p0] = b; g_clist[p0] = 1.0f;
    int o1 = g_idx1[b];
    int p1 = atomicAdd(&g_cnt[o1], 1);
    g_blist[p1] = b; g_clist[p1] = -ANTI;
}

// ---------------- ds = yl@x - xx*W, and nc = max|ds| (CSR) ----------------
__global__ __launch_bounds__(256)
void update_kernel(const float* __restrict__ x, const float* __restrict__ w,
                   const float* __restrict__ y, int OUT) {
    const int o   = blockIdx.x;
    const int tid = threadIdx.x;
    const int start = g_rowptr[o];
    const int end   = g_rowptr[o + 1];

    __shared__ float sxx;
    if (tid == 0) sxx = 0.f;
    __syncthreads();

    float xxloc = 0.f;
    for (int m = start + tid; m < end; m += 256)
        xxloc += g_clist[m] * y[(size_t)g_blist[m] * OUT_F + o];
    #pragma unroll
    for (int off = 16; off > 0; off >>= 1)
        xxloc += __shfl_xor_sync(0xffffffffu, xxloc, off);
    if ((tid & 31) == 0 && xxloc != 0.f) atomicAdd(&sxx, xxloc);
    __syncthreads();
    const float xx = sxx;

    float4 acc = make_float4(0.f, 0.f, 0.f, 0.f);
    for (int m = start; m < end; m++) {
        const float c = g_clist[m];
        const float4 xv = reinterpret_cast<const float4*>(
            x + (size_t)g_blist[m] * IN_F)[tid];
        acc.x = fmaf(c, xv.x, acc.x);
        acc.y = fmaf(c, xv.y, acc.y);
        acc.z = fmaf(c, xv.z, acc.z);
        acc.w = fmaf(c, xv.w, acc.w);
    }

    const float4 wv = reinterpret_cast<const float4*>(w + (size_t)o * IN_F)[tid];
    float4 d;
    d.x = acc.x - xx * wv.x;
    d.y = acc.y - xx * wv.y;
    d.z = acc.z - xx * wv.z;
    d.w = acc.w - xx * wv.w;
    reinterpret_cast<float4*>(g_ds + (size_t)o * IN_F)[tid] = d;

    float lmax = fmaxf(fmaxf(fabsf(d.x), fabsf(d.y)), fmaxf(fabsf(d.z), fabsf(d.w)));
    #pragma unroll
    for (int off = 16; off > 0; off >>= 1)
        lmax = fmaxf(lmax, __shfl_xor_sync(0xffffffffu, lmax, off));
    __shared__ float smax[8];
    if ((tid & 31) == 0) smax[tid >> 5] = lmax;
    __syncthreads();
    if (tid == 0) {
        float m = smax[0];
        #pragma unroll
        for (int k = 1; k < 8; k++) m = fmaxf(m, smax[k]);
        atomicMax(&g_nc, __float_as_uint(m));
    }
}

// ---------------- new_w = w + LR * ds / nc ----------------
__global__ __launch_bounds__(256)
void finalize_kernel(const float4* __restrict__ w4, float4* __restrict__ neww4, int n4) {
    const float inv = LR / __uint_as_float(g_nc);
    int i = blockIdx.x * blockDim.x + threadIdx.x;
    if (i < n4) {
        const float4* ds4 = reinterpret_cast<const float4*>(g_ds);
        float4 d = ds4[i];
        float4 v = w4[i];
        v.x = fmaf(d.x, inv, v.x);
        v.y = fmaf(d.y, inv, v.y);
        v.z = fmaf(d.z, inv, v.z);
        v.w = fmaf(d.w, inv, v.w);
        neww4[i] = v;
    }
}

// ---------------- launch ----------------
extern "C" void kernel_launch(void* const* d_in, const int* in_sizes, int n_in,
                              void* d_out, int out_size) {
    const float* x = (const float*)d_in[0];
    const float* w = (const float*)d_in[1];
    if (n_in >= 2 && in_sizes[0] == OUT_F * IN_F && in_sizes[1] == BATCH * IN_F) {
        w = (const float*)d_in[0];
        x = (const float*)d_in[1];
    }

    float* y_out = (float*)d_out;                       // [BATCH, OUT_F]
    float* w_out = y_out + (size_t)BATCH * OUT_F;       // [OUT_F, IN_F]

    __nv_bfloat16 *xhi, *xlo, *whi, *wlo;
    cudaGetSymbolAddress((void**)&xhi, g_xhi);
    cudaGetSymbolAddress((void**)&xlo, g_xlo);
    cudaGetSymbolAddress((void**)&whi, g_whi);
    cudaGetSymbolAddress((void**)&wlo, g_wlo);

    // 0) fused bf16 splits (+ nc/counter reset)
    {
        int n4x = BATCH * IN_F / 4;
        int n4t = n4x + OUT_F * IN_F / 4;
        split_bf16_fused<<<(n4t + 255) / 256, 256>>>(
            (const float4*)x, (const float4*)w,
            (uint2*)xhi, (uint2*)xlo, (uint2*)whi, (uint2*)wlo, n4x, n4t);
    }
    // 1) y = x @ W^T via bf16 mma.sync (128x128 tiles, 2 CTAs/SM)
    {
        cudaFuncSetAttribute(gemm_bf16_kernel,
                             cudaFuncAttributeMaxDynamicSharedMemorySize, SMEM_GEMM);
        dim3 grid(OUT_F / BN_T, BATCH / BM_T);
        gemm_bf16_kernel<<<grid, 256, SMEM_GEMM>>>(xhi, xlo, whi, wlo, y_out);
    }
    // 2) top-2 per batch row + match counting
    top2_kernel<<<BATCH / 8, 256>>>(y_out);
    // 3) CSR build: scan + fill
    scan_kernel<<<1, 1024>>>();
    fill_kernel<<<BATCH / 256, 256>>>();
    // 4) ds + global max (CSR-driven)
    update_kernel<<<OUT_F, 256>>>(x, w, y_out, OUT_F);
    // 5) finalize
    {
        int n4 = OUT_F * IN_F / 4;
        finalize_kernel<<<(n4 + 255) / 256, 256>>>((const float4*)w, (float4*)w_out, n4);
    }
}

// round 12
// speedup vs baseline: 2.7525x; 1.0425x over previous
#include <cuda_runtime.h>
#include <cuda_bf16.h>
#include <math_constants.h>
#include <cstdint>

// Problem constants
#define IN_F   1024
#define OUT_F  2048
#define BATCH  8192
#define LR     0.02f
#define ANTI   0.4f
#define PREC   1e-30f

// ---------------- scratch (no allocations allowed) ----------------
__device__ float          g_ds[(size_t)OUT_F * IN_F];
__device__ int            g_idx0[BATCH];
__device__ int            g_idx1[BATCH];
__device__ unsigned int   g_nc;
__device__ int            g_cnt[OUT_F];        // counts, then segment cursors
__device__ int            g_rowptr[OUT_F + 1];
__device__ int            g_blist[2 * BATCH];
__device__ float          g_clist[2 * BATCH];
// bf16 split matrices
__device__ __nv_bfloat16  g_xhi[(size_t)BATCH * IN_F];
__device__ __nv_bfloat16  g_xlo[(size_t)BATCH * IN_F];
__device__ __nv_bfloat16  g_whi[(size_t)OUT_F * IN_F];
__device__ __nv_bfloat16  g_wlo[(size_t)OUT_F * IN_F];

// ================= helpers =================
__device__ __forceinline__ uint32_t smem_u32(const void* p) {
    uint32_t a;
    asm("{ .reg .u64 t; cvta.to.shared.u64 t, %1; cvt.u32.u64 %0, t; }" : "=r"(a) : "l"(p));
    return a;
}
__device__ __forceinline__ void cp16(uint32_t sm, const void* g) {
    asm volatile("cp.async.cg.shared.global [%0], [%1], 16;" :: "r"(sm), "l"(g) : "memory");
}
__device__ __forceinline__ void cp_commit() {
    asm volatile("cp.async.commit_group;" ::: "memory");
}
template <int N>
__device__ __forceinline__ void cp_wait() {
    asm volatile("cp.async.wait_group %0;" :: "n"(N) : "memory");
}
__device__ __forceinline__ void mma_bf16(float* d, const uint32_t* a, const uint32_t* b) {
    asm volatile(
        "mma.sync.aligned.m16n8k16.row.col.f32.bf16.bf16.f32 "
        "{%0,%1,%2,%3}, {%4,%5,%6,%7}, {%8,%9}, {%0,%1,%2,%3};"
        : "+f"(d[0]), "+f"(d[1]), "+f"(d[2]), "+f"(d[3])
        : "r"(a[0]), "r"(a[1]), "r"(a[2]), "r"(a[3]), "r"(b[0]), "r"(b[1]));
}
__device__ __forceinline__ void ldsm4(uint32_t& r0, uint32_t& r1, uint32_t& r2, uint32_t& r3,
                                      uint32_t addr) {
    asm volatile("ldmatrix.sync.aligned.m8n8.x4.shared.b16 {%0,%1,%2,%3}, [%4];"
                 : "=r"(r0), "=r"(r1), "=r"(r2), "=r"(r3) : "r"(addr));
}

// ================= fused split kernel: {x,w} -> (bf16 hi, bf16 lo) =========
__global__ __launch_bounds__(256)
void split_bf16_fused(const float4* __restrict__ x4, const float4* __restrict__ w4,
                      uint2* __restrict__ xhi, uint2* __restrict__ xlo,
                      uint2* __restrict__ whi, uint2* __restrict__ wlo,
                      int n4x, int n4tot) {
    int i = blockIdx.x * blockDim.x + threadIdx.x;
    if (i == 0) g_nc = __float_as_uint(PREC);   // reset for this launch
    if (i < OUT_F) g_cnt[i] = 0;                // zero match counters
    if (i >= n4tot) return;
    const float4* src; uint2 *hi, *lo; int idx;
    if (i < n4x) { src = x4; hi = xhi; lo = xlo; idx = i; }
    else         { src = w4; hi = whi; lo = wlo; idx = i - n4x; }
    float4 v = src[idx];
    __nv_bfloat16 h0 = __float2bfloat16(v.x);
    __nv_bfloat16 h1 = __float2bfloat16(v.y);
    __nv_bfloat16 h2 = __float2bfloat16(v.z);
    __nv_bfloat16 h3 = __float2bfloat16(v.w);
    __nv_bfloat16 l0 = __float2bfloat16(v.x - __bfloat162float(h0));
    __nv_bfloat16 l1 = __float2bfloat16(v.y - __bfloat162float(h1));
    __nv_bfloat16 l2 = __float2bfloat16(v.z - __bfloat162float(h2));
    __nv_bfloat16 l3 = __float2bfloat16(v.w - __bfloat162float(h3));
    __nv_bfloat162 hp0 = __halves2bfloat162(h0, h1);
    __nv_bfloat162 hp1 = __halves2bfloat162(h2, h3);
    __nv_bfloat162 lp0 = __halves2bfloat162(l0, l1);
    __nv_bfloat162 lp1 = __halves2bfloat162(l2, l3);
    uint2 hv, lv;
    hv.x = *reinterpret_cast<uint32_t*>(&hp0); hv.y = *reinterpret_cast<uint32_t*>(&hp1);
    lv.x = *reinterpret_cast<uint32_t*>(&lp0); lv.y = *reinterpret_cast<uint32_t*>(&lp1);
    hi[idx] = hv; lo[idx] = lv;
}

// ================= bf16 mma.sync GEMM (3-product split folded into K) =====
// 128x128 CTA tiles, 2 CTAs/SM, 3-stage cp.async pipeline, 1 barrier/chunk.
#define BM_T 128
#define BN_T 128
#define ROWB 144u
#define STAGE_B ((BM_T + BN_T) * ROWB)   // 256*144 = 36864
#define NSTAGEG 3
#define NCHUNKG 48
#define SMEM_GEMM (NSTAGEG * STAGE_B)    // 110592 (x2 CTAs = 221184 <= 228KB/SM)

__global__ __launch_bounds__(256, 2)
void gemm_bf16_kernel(const __nv_bfloat16* __restrict__ Xhi,
                      const __nv_bfloat16* __restrict__ Xlo,
                      const __nv_bfloat16* __restrict__ Whi,
                      const __nv_bfloat16* __restrict__ Wlo,
                      float* __restrict__ C) {
    extern __shared__ char smem[];
    const uint32_t sb = smem_u32(smem);
    const int tid  = threadIdx.x;
    const int wid  = tid >> 5;
    const int lane = tid & 31;
    const int gr   = lane >> 2;
    const int tig  = lane & 3;
    const int wm   = wid & 1;      // 2 warp rows (64 each)
    const int wn   = wid >> 1;     // 4 warp cols (32 each)
    const int m0 = blockIdx.y * BM_T;
    const int n0 = blockIdx.x * BN_T;

    const uint32_t aoff = (uint32_t)(wm * 64 + (lane & 15)) * ROWB + (uint32_t)(lane >> 4) * 16;
    const uint32_t boff = (uint32_t)(wn * 32 + ((lane >> 4) * 8) + (lane & 7)) * ROWB
                        + (uint32_t)((lane >> 3) & 1) * 16;

    auto issue_chunk = [&](int s) {
        const int region = s >> 4;
        const int kb = (s & 15) * 128;
        const __nv_bfloat16* Asrc = (region == 1) ? Xlo : Xhi;
        const __nv_bfloat16* Bsrc = (region == 2) ? Wlo : Whi;
        const uint32_t base = sb + (uint32_t)(s % NSTAGEG) * STAGE_B;
        #pragma unroll
        for (int c = 0; c < 8; c++) {
            int idx = tid + c * 256;           // 0..2047
            int row = idx >> 3, g = idx & 7;   // row 0..255
            const char* gp;
            if (row < BM_T)
                gp = (const char*)Asrc + (size_t)(m0 + row) * (IN_F * 2) + kb + g * 16;
            else
                gp = (const char*)Bsrc + (size_t)(n0 + row - BM_T) * (IN_F * 2) + kb + g * 16;
            cp16(base + row * ROWB + g * 16, gp);
        }
        cp_commit();
    };

    float acc[4][4][4];
    #pragma unroll
    for (int i = 0; i < 4; i++)
        #pragma unroll
        for (int j = 0; j < 4; j++)
            #pragma unroll
            for (int r = 0; r < 4; r++) acc[i][j][r] = 0.f;

    issue_chunk(0);
    issue_chunk(1);

    for (int s = 0; s < NCHUNKG; s++) {
        if (s == NCHUNKG - 1) cp_wait<0>(); else cp_wait<1>();
        __syncthreads();
        // stage (s+2)%3 was fully consumed before the barrier above
        if (s + 2 < NCHUNKG) issue_chunk(s + 2);

        const uint32_t base = sb + (uint32_t)(s % NSTAGEG) * STAGE_B;
        const uint32_t aB = base + aoff;
        const uint32_t bB = base + BM_T * ROWB + boff;

        #pragma unroll
        for (int ks = 0; ks < 4; ks++) {
            const uint32_t k0b = (uint32_t)ks * 32;
            uint32_t a[4][4], b[4][2];
            #pragma unroll
            for (int i = 0; i < 4; i++)
                ldsm4(a[i][0], a[i][1], a[i][2], a[i][3],
                      aB + (uint32_t)i * (16 * ROWB) + k0b);
            ldsm4(b[0][0], b[0][1], b[1][0], b[1][1], bB + k0b);
            ldsm4(b[2][0], b[2][1], b[3][0], b[3][1], bB + 16 * ROWB + k0b);
            #pragma unroll
            for (int i = 0; i < 4; i++)
                #pragma unroll
                for (int j = 0; j < 4; j++)
                    mma_bf16(acc[i][j], a[i], b[j]);
        }
    }

    #pragma unroll
    for (int i = 0; i < 4; i++) {
        int r0 = m0 + wm * 64 + i * 16 + gr;
        #pragma unroll
        for (int j = 0; j < 4; j++) {
            int cc = n0 + wn * 32 + j * 8 + 2 * tig;
            *reinterpret_cast<float2*>(C + (size_t)r0 * OUT_F + cc) =
                make_float2(acc[i][j][0], acc[i][j][1]);
            *reinterpret_cast<float2*>(C + (size_t)(r0 + 8) * OUT_F + cc) =
                make_float2(acc[i][j][2], acc[i][j][3]);
        }
    }
}

// ---------------- Top-2 per batch row (warp per row) + match counting -----
__device__ __forceinline__ void merge_top2(float& av1, int& ai1, float& av2, int& ai2,
                                           float bv1, int bi1, float bv2, int bi2) {
    if (bv1 > av1 || (bv1 == av1 && bi1 < ai1)) {
        float nv2; int ni2;
        if (av1 > bv2 || (av1 == bv2 && ai1 < bi2)) { nv2 = av1; ni2 = ai1; }
        else                                         { nv2 = bv2; ni2 = bi2; }
        av1 = bv1; ai1 = bi1; av2 = nv2; ai2 = ni2;
    } else {
        if (bv1 > av2 || (bv1 == av2 && bi1 < ai2)) { av2 = bv1; ai2 = bi1; }
    }
}

__global__ __launch_bounds__(256)
void top2_kernel(const float* __restrict__ y) {
    const int warp = threadIdx.x >> 5;
    const int lane = threadIdx.x & 31;
    const int row  = blockIdx.x * 8 + warp;

    const float4* r4 = reinterpret_cast<const float4*>(y + (size_t)row * OUT_F);
    float v1 = -CUDART_INF_F, v2 = -CUDART_INF_F;
    int   i1 = 0x7fffffff,    i2 = 0x7fffffff;

    auto upd = [&](float v, int j) {
        if (v > v1) { v2 = v1; i2 = i1; v1 = v; i1 = j; }
        else if (v > v2) { v2 = v; i2 = j; }
    };
    #pragma unroll
    for (int k = 0; k < 16; k++) {
        int j4 = lane + 32 * k;
        float4 v = r4[j4];
        int jb = 4 * j4;
        upd(v.x, jb); upd(v.y, jb + 1); upd(v.z, jb + 2); upd(v.w, jb + 3);
    }

    #pragma unroll
    for (int off = 16; off > 0; off >>= 1) {
        float ov1 = __shfl_xor_sync(0xffffffffu, v1, off);
        int   oi1 = __shfl_xor_sync(0xffffffffu, i1, off);
        float ov2 = __shfl_xor_sync(0xffffffffu, v2, off);
        int   oi2 = __shfl_xor_sync(0xffffffffu, i2, off);
        merge_top2(v1, i1, v2, i2, ov1, oi1, ov2, oi2);
    }
    if (lane == 0) {
        g_idx0[row] = i1; g_idx1[row] = i2;
        atomicAdd(&g_cnt[i1], 1);
        atomicAdd(&g_cnt[i2], 1);
    }
}

// ---------------- exclusive scan of g_cnt -> g_rowptr (shfl-based) --------
__global__ __launch_bounds__(1024)
void scan_kernel() {
    const int t = threadIdx.x;              // 0..1023, pair (2t, 2t+1)
    int v0 = g_cnt[2 * t], v1 = g_cnt[2 * t + 1];
    int s = v0 + v1;
    int incl = s;
    #pragma unroll
    for (int off = 1; off < 32; off <<= 1) {
        int n = __shfl_up_sync(0xffffffffu, incl, off);
        if ((t & 31) >= off) incl += n;
    }
    __shared__ int wsum[32];
    if ((t & 31) == 31) wsum[t >> 5] = incl;
    __syncthreads();
    if (t < 32) {
        int w = wsum[t];
        int wincl = w;
        #pragma unroll
        for (int off = 1; off < 32; off <<= 1) {
            int n = __shfl_up_sync(0xffffffffu, wincl, off);
            if (t >= off) wincl += n;
        }
        wsum[t] = wincl - w;                // exclusive warp base
    }
    __syncthreads();
    int base = wsum[t >> 5] + (incl - s);   // exclusive prefix of this pair
    g_rowptr[2 * t]     = base;
    g_rowptr[2 * t + 1] = base + v0;
    g_cnt[2 * t]        = base;             // segment cursors for fill
    g_cnt[2 * t + 1]    = base + v0;
    if (t == 1023) g_rowptr[OUT_F] = base + s;
}

// ---------------- fill CSR lists ------------------------------------------
__global__ __launch_bounds__(256)
void fill_kernel() {
    int b = blockIdx.x * blockDim.x + threadIdx.x;
    if (b >= BATCH) return;
    int o0 = g_idx0[b];
    int p0 = atomicAdd(&g_cnt[o0], 1);
    g_blist[p0] = b; g_clist[p0] = 1.0f;
    int o1 = g_idx1[b];
    int p1 = atomicAdd(&g_cnt[o1], 1);
    g_blist[p1] = b; g_clist[p1] = -ANTI;
}

// ---------------- ds = yl@x - xx*W, and nc = max|ds| (CSR) ----------------
__global__ __launch_bounds__(256)
void update_kernel(const float* __restrict__ x, const float* __restrict__ w,
                   const float* __restrict__ y, int OUT) {
    const int o   = blockIdx.x;
    const int tid = threadIdx.x;
    const int start = g_rowptr[o];
    const int end   = g_rowptr[o + 1];

    __shared__ float sxx;
    if (tid == 0) sxx = 0.f;
    __syncthreads();

    float xxloc = 0.f;
    for (int m = start + tid; m < end; m += 256)
        xxloc += g_clist[m] * y[(size_t)g_blist[m] * OUT_F + o];
    #pragma unroll
    for (int off = 16; off > 0; off >>= 1)
        xxloc += __shfl_xor_sync(0xffffffffu, xxloc, off);
    if ((tid & 31) == 0 && xxloc != 0.f) atomicAdd(&sxx, xxloc);
    __syncthreads();
    const float xx = sxx;

    float4 acc = make_float4(0.f, 0.f, 0.f, 0.f);
    for (int m = start; m < end; m++) {
        const float c = g_clist[m];
        const float4 xv = reinterpret_cast<const float4*>(
            x + (size_t)g_blist[m] * IN_F)[tid];
        acc.x = fmaf(c, xv.x, acc.x);
        acc.y = fmaf(c, xv.y, acc.y);
        acc.z = fmaf(c, xv.z, acc.z);
        acc.w = fmaf(c, xv.w, acc.w);
    }

    const float4 wv = reinterpret_cast<const float4*>(w + (size_t)o * IN_F)[tid];
    float4 d;
    d.x = acc.x - xx * wv.x;
    d.y = acc.y - xx * wv.y;
    d.z = acc.z - xx * wv.z;
    d.w = acc.w - xx * wv.w;
    reinterpret_cast<float4*>(g_ds + (size_t)o * IN_F)[tid] = d;

    float lmax = fmaxf(fmaxf(fabsf(d.x), fabsf(d.y)), fmaxf(fabsf(d.z), fabsf(d.w)));
    #pragma unroll
    for (int off = 16; off > 0; off >>= 1)
        lmax = fmaxf(lmax, __shfl_xor_sync(0xffffffffu, lmax, off));
    __shared__ float smax[8];
    if ((tid & 31) == 0) smax[tid >> 5] = lmax;
    __syncthreads();
    if (tid == 0) {
        float m = smax[0];
        #pragma unroll
        for (int k = 1; k < 8; k++) m = fmaxf(m, smax[k]);
        atomicMax(&g_nc, __float_as_uint(m));
    }
}

// ---------------- new_w = w + LR * ds / nc ----------------
__global__ __launch_bounds__(256)
void finalize_kernel(const float4* __restrict__ w4, float4* __restrict__ neww4, int n4) {
    const float inv = LR / __uint_as_float(g_nc);
    int i = blockIdx.x * blockDim.x + threadIdx.x;
    if (i < n4) {
        const float4* ds4 = reinterpret_cast<const float4*>(g_ds);
        float4 d = ds4[i];
        float4 v = w4[i];
        v.x = fmaf(d.x, inv, v.x);
        v.y = fmaf(d.y, inv, v.y);
        v.z = fmaf(d.z, inv, v.z);
        v.w = fmaf(d.w, inv, v.w);
        neww4[i] = v;
    }
}

// ---------------- launch ----------------
extern "C" void kernel_launch(void* const* d_in, const int* in_sizes, int n_in,
                              void* d_out, int out_size) {
    const float* x = (const float*)d_in[0];
    const float* w = (const float*)d_in[1];
    if (n_in >= 2 && in_sizes[0] == OUT_F * IN_F && in_sizes[1] == BATCH * IN_F) {
        w = (const float*)d_in[0];
        x = (const float*)d_in[1];
    }

    float* y_out = (float*)d_out;                       // [BATCH, OUT_F]
    float* w_out = y_out + (size_t)BATCH * OUT_F;       // [OUT_F, IN_F]

    __nv_bfloat16 *xhi, *xlo, *whi, *wlo;
    cudaGetSymbolAddress((void**)&xhi, g_xhi);
    cudaGetSymbolAddress((void**)&xlo, g_xlo);
    cudaGetSymbolAddress((void**)&whi, g_whi);
    cudaGetSymbolAddress((void**)&wlo, g_wlo);

    // 0) fused bf16 splits (+ nc/counter reset)
    {
        int n4x = BATCH * IN_F / 4;
        int n4t = n4x + OUT_F * IN_F / 4;
        split_bf16_fused<<<(n4t + 255) / 256, 256>>>(
            (const float4*)x, (const float4*)w,
            (uint2*)xhi, (uint2*)xlo, (uint2*)whi, (uint2*)wlo, n4x, n4t);
    }
    // 1) y = x @ W^T via bf16 mma.sync (128x128 tiles, 2 CTAs/SM, 3 stages)
    {
        cudaFuncSetAttribute(gemm_bf16_kernel,
                             cudaFuncAttributeMaxDynamicSharedMemorySize, SMEM_GEMM);
        dim3 grid(OUT_F / BN_T, BATCH / BM_T);
        gemm_bf16_kernel<<<grid, 256, SMEM_GEMM>>>(xhi, xlo, whi, wlo, y_out);
    }
    // 2) top-2 per batch row + match counting
    top2_kernel<<<BATCH / 8, 256>>>(y_out);
    // 3) CSR build: scan + fill
    scan_kernel<<<1, 1024>>>();
    fill_kernel<<<BATCH / 256, 256>>>();
    // 4) ds + global max (CSR-driven)
    update_kernel<<<OUT_F, 256>>>(x, w, y_out, OUT_F);
    // 5) finalize
    {
        int n4 = OUT_F * IN_F / 4;
        finalize_kernel<<<(n4 + 255) / 256, 256>>>((const float4*)w, (float4*)w_out, n4);
    }
}